// round 1
// baseline (speedup 1.0000x reference)
#include <cuda_runtime.h>
#include <cstddef>

// Problem constants
#define HH 512
#define WW 512
#define BB 8
constexpr int HW = HH * WW;

// ---------------- scratch (static device globals; no allocation) ----------------
__device__ float g_B1[(size_t)BB * 64 * HW];   // body1 / body3 reuse (sized for 64 to be safe)
__device__ float g_B2[(size_t)BB * 64 * HW];   // body2
__device__ float g_HP0[(size_t)BB * 4 * HW];   // head pre-activations
__device__ float g_HP1[(size_t)BB * 4 * HW];
__device__ float g_HP2[(size_t)BB * 4 * HW];
__device__ float g_G[3 * BB * 4];
__device__ float g_S[3 * BB * 4];
__device__ float g_HB5[(size_t)BB * 3 * HW];   // horizontal blur partials
__device__ float g_HB15[(size_t)BB * 3 * HW];
__device__ float g_HB25[(size_t)BB * 3 * HW];
__device__ float g_TX[(size_t)BB * 3 * HW];    // intermediate fused image

// ---------------- 3x3 conv (zero pad=1) + bias + optional PReLU ----------------
// Block: 256 threads, output tile 64(w) x 16(h) x 4 output channels.
// Thread: pixels (tx, tx+32) x (2ty, 2ty+1)  -> 2x2 micro-tile, 4 out channels.
template<int CIN, int CHUNK, int COUT>
__global__ __launch_bounds__(256) void conv3x3_k(
    const float* __restrict__ in, const float* __restrict__ wgt,
    const float* __restrict__ bias, const float* __restrict__ pr,
    float* __restrict__ out)
{
    constexpr int NCB = COUT / 4;
    __shared__ float s_in[CHUNK][18][66];
    __shared__ float s_w[4][CHUNK][9];

    const int tid = threadIdx.x;
    const int tx = tid & 31, ty = tid >> 5;
    const int bz = blockIdx.z;
    const int cb = bz % NCB, b = bz / NCB;
    const int obase = cb * 4;
    const int x0 = blockIdx.x * 64, y0 = blockIdx.y * 16;

    float acc[4][2][2] = {};

    for (int c0 = 0; c0 < CIN; c0 += CHUNK) {
        // load weights for this chunk
        for (int i = tid; i < 4 * CHUNK * 9; i += 256) {
            int o = i / (CHUNK * 9);
            int r = i % (CHUNK * 9);
            int c = r / 9, t = r % 9;
            s_w[o][c][t] = wgt[((size_t)(obase + o) * CIN + c0 + c) * 9 + t];
        }
        // load input tile (with halo, zero-padded)
        for (int i = tid; i < CHUNK * 18 * 66; i += 256) {
            int c  = i / (18 * 66);
            int r2 = i % (18 * 66);
            int rr = r2 / 66, cc = r2 % 66;
            int gy = y0 + rr - 1, gx = x0 + cc - 1;
            float v = 0.f;
            if ((unsigned)gy < HH && (unsigned)gx < WW)
                v = in[((size_t)(b * CIN + c0 + c)) * HW + (size_t)gy * WW + gx];
            s_in[c][rr][cc] = v;
        }
        __syncthreads();

        #pragma unroll
        for (int c = 0; c < CHUNK; c++) {
            float vL[4][3], vR[4][3];
            #pragma unroll
            for (int rr = 0; rr < 4; rr++)
                #pragma unroll
                for (int dx = 0; dx < 3; dx++) {
                    vL[rr][dx] = s_in[c][2 * ty + rr][tx + dx];
                    vR[rr][dx] = s_in[c][2 * ty + rr][tx + 32 + dx];
                }
            #pragma unroll
            for (int o = 0; o < 4; o++)
                #pragma unroll
                for (int dy = 0; dy < 3; dy++)
                    #pragma unroll
                    for (int dx = 0; dx < 3; dx++) {
                        float wv = s_w[o][c][dy * 3 + dx];
                        acc[o][0][0] += vL[dy][dx] * wv;
                        acc[o][1][0] += vL[dy + 1][dx] * wv;
                        acc[o][0][1] += vR[dy][dx] * wv;
                        acc[o][1][1] += vR[dy + 1][dx] * wv;
                    }
        }
        __syncthreads();
    }

    const bool hasp = (pr != nullptr);
    const float a = hasp ? pr[0] : 0.f;
    #pragma unroll
    for (int o = 0; o < 4; o++) {
        float bo = bias[obase + o];
        #pragma unroll
        for (int py = 0; py < 2; py++) {
            int gy = y0 + 2 * ty + py;
            #pragma unroll
            for (int px = 0; px < 2; px++) {
                int gx = x0 + tx + px * 32;
                float v = acc[o][py][px] + bo;
                if (hasp && v < 0.f) v *= a;
                out[((size_t)(b * COUT + obase + o)) * HW + (size_t)gy * WW + gx] = v;
            }
        }
    }
}

// ---------------- global average pool per (b, channel) ----------------
__global__ __launch_bounds__(256) void gap_k(const float* __restrict__ hp, float* __restrict__ g)
{
    __shared__ float sm[256];
    const int bc = blockIdx.x;
    const float4* p = (const float4*)(hp + (size_t)bc * HW);
    float s = 0.f;
    for (int i = threadIdx.x; i < HW / 4; i += 256) {
        float4 v = p[i];
        s += (v.x + v.y) + (v.z + v.w);
    }
    sm[threadIdx.x] = s;
    __syncthreads();
    for (int st = 128; st > 0; st >>= 1) {
        if (threadIdx.x < st) sm[threadIdx.x] += sm[threadIdx.x + st];
        __syncthreads();
    }
    if (threadIdx.x == 0) g[bc] = sm[0] * (1.0f / HW);
}

// ---------------- SE: s = sigmoid(c2 @ relu(c1 @ g)) ----------------
__global__ void se_k(const float* __restrict__ g, const float* __restrict__ c1,
                     const float* __restrict__ c2, float* __restrict__ s)
{
    __shared__ float t[BB][4];
    int tid = threadIdx.x;
    if (tid < BB * 4) {
        int b = tid >> 2, c = tid & 3;
        float v = 0.f;
        #pragma unroll
        for (int k = 0; k < 4; k++) v += c1[c * 4 + k] * g[b * 4 + k];
        t[b][c] = fmaxf(v, 0.f);
    }
    __syncthreads();
    if (tid < BB * 4) {
        int b = tid >> 2, c = tid & 3;
        float v = 0.f;
        #pragma unroll
        for (int k = 0; k < 4; k++) v += c2[c * 4 + k] * t[b][k];
        s[b * 4 + c] = 1.f / (1.f + __expf(-v));
    }
}

// ---------------- horizontal box partial sums (k=5,15,25), zero pad ----------------
__global__ __launch_bounds__(256) void hblur_k(const float* __restrict__ src,
                                               float* __restrict__ o5,
                                               float* __restrict__ o15,
                                               float* __restrict__ o25)
{
    __shared__ float row[280];
    const int bc = blockIdx.z;
    const int y = blockIdx.y;
    const int xs = blockIdx.x * 256;
    const size_t base = (size_t)bc * HW + (size_t)y * WW;
    for (int i = threadIdx.x; i < 280; i += 256) {
        int gx = xs + i - 12;
        row[i] = ((unsigned)gx < WW) ? src[base + gx] : 0.f;
    }
    __syncthreads();
    const int cx = threadIdx.x + 12;
    float s = row[cx - 2] + row[cx - 1] + row[cx] + row[cx + 1] + row[cx + 2];
    o5[base + xs + threadIdx.x] = s;
    #pragma unroll
    for (int d = 3; d <= 7; d++) s += row[cx - d] + row[cx + d];
    o15[base + xs + threadIdx.x] = s;
    #pragma unroll
    for (int d = 8; d <= 12; d++) s += row[cx - d] + row[cx + d];
    o25[base + xs + threadIdx.x] = s;
}

// ---------------- fused: softmax(hp*s) weights + vertical box + combine ----------------
__global__ __launch_bounds__(256) void fuse_k(
    const float* __restrict__ xin, const float* __restrict__ hp, const float* __restrict__ sv,
    const float* __restrict__ b5, const float* __restrict__ b15, const float* __restrict__ b25,
    float* __restrict__ out)
{
    const int x = blockIdx.x * 32 + threadIdx.x;
    const int y = blockIdx.y * 8 + threadIdx.y;
    const int z = blockIdx.z;
    const int c = z % 3, b = z / 3;

    const size_t hbase = ((size_t)b * 4) * HW + (size_t)y * WW + x;
    float e0 = hp[hbase] * sv[b * 4 + 0];
    float e1 = hp[hbase + (size_t)HW] * sv[b * 4 + 1];
    float e2 = hp[hbase + (size_t)2 * HW] * sv[b * 4 + 2];
    float e3 = hp[hbase + (size_t)3 * HW] * sv[b * 4 + 3];
    float m = fmaxf(fmaxf(e0, e1), fmaxf(e2, e3));
    float w0 = __expf(e0 - m), w1 = __expf(e1 - m), w2 = __expf(e2 - m), w3 = __expf(e3 - m);
    float inv = 1.f / (w0 + w1 + w2 + w3);

    const size_t cb = ((size_t)(b * 3 + c)) * HW;
    float v5 = 0.f, v15 = 0.f, v25 = 0.f;
    #pragma unroll
    for (int d = -12; d <= 12; d++) {
        int yy = y + d;
        if ((unsigned)yy < HH) {
            size_t idx = cb + (size_t)yy * WW + x;
            int ad = d < 0 ? -d : d;
            v25 += b25[idx];
            if (ad <= 7) v15 += b15[idx];
            if (ad <= 2) v5 += b5[idx];
        }
    }
    float o = (w0 * inv) * xin[cb + (size_t)y * WW + x]
            + (w1 * inv) * (v5 * (1.f / 25.f))
            + (w2 * inv) * (v15 * (1.f / 225.f))
            + (w3 * inv) * (v25 * (1.f / 625.f));
    out[cb + (size_t)y * WW + x] = o;
}

// ---------------- launch ----------------
extern "C" void kernel_launch(void* const* d_in, const int* in_sizes, int n_in,
                              void* d_out, int out_size)
{
    const float* x   = (const float*)d_in[0];
    const float* bw1 = (const float*)d_in[1];
    const float* bb1 = (const float*)d_in[2];
    const float* a1  = (const float*)d_in[3];
    const float* bw2 = (const float*)d_in[4];
    const float* bb2 = (const float*)d_in[5];
    const float* a2  = (const float*)d_in[6];
    const float* bw3 = (const float*)d_in[7];
    const float* bb3 = (const float*)d_in[8];
    const float* a3  = (const float*)d_in[9];
    const float* hw_[3]  = { (const float*)d_in[10], (const float*)d_in[14], (const float*)d_in[18] };
    const float* hb_[3]  = { (const float*)d_in[11], (const float*)d_in[15], (const float*)d_in[19] };
    const float* hc1_[3] = { (const float*)d_in[12], (const float*)d_in[16], (const float*)d_in[20] };
    const float* hc2_[3] = { (const float*)d_in[13], (const float*)d_in[17], (const float*)d_in[21] };

    float *B1, *B2, *HP[3], *G, *S, *HB5, *HB15, *HB25, *TX;
    cudaGetSymbolAddress((void**)&B1, g_B1);
    cudaGetSymbolAddress((void**)&B2, g_B2);
    cudaGetSymbolAddress((void**)&HP[0], g_HP0);
    cudaGetSymbolAddress((void**)&HP[1], g_HP1);
    cudaGetSymbolAddress((void**)&HP[2], g_HP2);
    cudaGetSymbolAddress((void**)&G, g_G);
    cudaGetSymbolAddress((void**)&S, g_S);
    cudaGetSymbolAddress((void**)&HB5, g_HB5);
    cudaGetSymbolAddress((void**)&HB15, g_HB15);
    cudaGetSymbolAddress((void**)&HB25, g_HB25);
    cudaGetSymbolAddress((void**)&TX, g_TX);

    const dim3 cgrid(8, 32, 0);

    // body
    conv3x3_k<3, 3, 32><<<dim3(8, 32, BB * 8), 256>>>(x, bw1, bb1, a1, B1);
    conv3x3_k<32, 8, 64><<<dim3(8, 32, BB * 16), 256>>>(B1, bw2, bb2, a2, B2);
    conv3x3_k<64, 8, 32><<<dim3(8, 32, BB * 8), 256>>>(B2, bw3, bb3, a3, B1);

    // heads: pre-activation maps + GAP + SE scales
    for (int i = 0; i < 3; i++) {
        conv3x3_k<32, 8, 4><<<dim3(8, 32, BB * 1), 256>>>(B1, hw_[i], hb_[i], nullptr, HP[i]);
        gap_k<<<BB * 4, 256>>>(HP[i], G + i * BB * 4);
        se_k<<<1, 32>>>(G + i * BB * 4, hc1_[i], hc2_[i], S + i * BB * 4);
    }

    // stage 1: x -> TX
    hblur_k<<<dim3(2, HH, BB * 3), 256>>>(x, HB5, HB15, HB25);
    fuse_k<<<dim3(16, 64, BB * 3), dim3(32, 8)>>>(x, HP[0], S + 0, HB5, HB15, HB25, TX);
    // stage 2: TX -> TX (in-place safe: fuse reads xin only at its own pixel)
    hblur_k<<<dim3(2, HH, BB * 3), 256>>>(TX, HB5, HB15, HB25);
    fuse_k<<<dim3(16, 64, BB * 3), dim3(32, 8)>>>(TX, HP[1], S + BB * 4, HB5, HB15, HB25, TX);
    // stage 3: TX -> out
    hblur_k<<<dim3(2, HH, BB * 3), 256>>>(TX, HB5, HB15, HB25);
    fuse_k<<<dim3(16, 64, BB * 3), dim3(32, 8)>>>(TX, HP[2], S + 2 * BB * 4, HB5, HB15, HB25,
                                                  (float*)d_out);
    (void)in_sizes; (void)n_in; (void)out_size;
}

// round 3
// speedup vs baseline: 2.1404x; 2.1404x over previous
#include <cuda_runtime.h>
#include <cstdint>
#include <cstddef>

#define HH 512
#define WW 512
#define BB 8
constexpr int HW = HH * WW;

// ---------------- scratch ----------------
__device__ float g_B1[(size_t)BB * 64 * HW];
__device__ float g_B2[(size_t)BB * 64 * HW];   // also reused as HPA (12ch head maps)
__device__ float g_G[3 * BB * 4];
__device__ float g_S[3 * BB * 4];
__device__ float g_HB5[(size_t)BB * 3 * HW];
__device__ float g_HB15[(size_t)BB * 3 * HW];
__device__ float g_HB25[(size_t)BB * 3 * HW];
__device__ float g_TX[(size_t)BB * 3 * HW];

// ---------------- helpers ----------------
__device__ __forceinline__ uint32_t f2tf32(float v) {
    uint32_t r;
    asm("cvt.rna.tf32.f32 %0, %1;" : "=r"(r) : "f"(v));
    return r;
}
__device__ __forceinline__ void mma8(float* d, const uint32_t* a, uint32_t b0, uint32_t b1) {
    asm volatile(
        "mma.sync.aligned.m16n8k8.row.col.f32.tf32.tf32.f32 "
        "{%0,%1,%2,%3}, {%4,%5,%6,%7}, {%8,%9}, {%0,%1,%2,%3};"
        : "+f"(d[0]), "+f"(d[1]), "+f"(d[2]), "+f"(d[3])
        : "r"(a[0]), "r"(a[1]), "r"(a[2]), "r"(a[3]), "r"(b0), "r"(b1));
}

// ================= tensor-core 3x3 conv via mma.sync tf32 =================
// Block: 256 threads (8 warps: 4 M-subtiles x 2 N-subtiles).
// Tile: M=128 pixels (x) x N=2*NSUB channels, iterated over 8 output rows (y).
// K = CIN per tap, 9 taps. Rolling 3-row input window in smem; all weights in smem.
// NSTR: padded N stride for weight smem (NSTR % 32 gives conflict-free banks).
template<int CIN, int COUT, int NSUB, int NSTR, bool H3>
__global__ __launch_bounds__(256) void mconv_k(
    const float* __restrict__ in,
    const float* __restrict__ wA, const float* __restrict__ wB2, const float* __restrict__ wC,
    const float* __restrict__ bA, const float* __restrict__ bB2, const float* __restrict__ bC,
    const float* __restrict__ pr, float* __restrict__ out)
{
    constexpr int NTOT = 2 * NSUB;
    constexpr int ROWF = 132;        // padded floats per smem row
    constexpr int CSTR = 3 * ROWF;   // 396 (396 % 32 == 12 -> conflict-free A frags)
    constexpr int NKS = CIN / 8;

    extern __shared__ float sm[];
    uint32_t* in_u = (uint32_t*)sm;                 // CIN * CSTR
    uint32_t* w_u  = (uint32_t*)(sm + CIN * CSTR);  // 9 * CIN * NSTR

    const int tid = threadIdx.x;
    const int lane = tid & 31;
    const int wid = tid >> 5;
    const int g = lane >> 2, tg = lane & 3;
    const int mbase = (wid >> 1) * 32;
    const int nbase = (wid & 1) * NSUB;
    const int x0 = blockIdx.x * 128;
    const int y0 = blockIdx.y * 8;
    const int b = blockIdx.z;
    const int outc = H3 ? 12 : COUT;

    // ---- stage all 9 tap weight slices: w_s[tap][c][n] (tf32) ----
    for (int i = tid; i < 9 * CIN * NTOT; i += 256) {
        const int tap = i / (CIN * NTOT);
        const int r = i % (CIN * NTOT);
        const int c = r / NTOT, n = r % NTOT;
        float v = 0.f;
        if (H3) {
            if (n < 12) {
                const float* wp = (n < 4) ? wA : (n < 8 ? wB2 : wC);
                v = wp[((size_t)(n & 3) * CIN + c) * 9 + tap];
            }
        } else if (n < COUT) {
            v = wA[((size_t)n * CIN + c) * 9 + tap];
        }
        w_u[tap * CIN * NSTR + c * NSTR + n] = f2tf32(v);
    }

    const float* inb = in + (size_t)b * CIN * HW;
    float* ob = out + (size_t)b * outc * HW;
    const float alpha = pr ? pr[0] : 0.f;

    #pragma unroll 1
    for (int yi = 0; yi < 8; yi++) {
        const int y = y0 + yi;
        __syncthreads();
        // rolling window: first iter loads rows y-1..y+1, later iters only y+1
        const int rlo = (yi == 0) ? (y - 1) : (y + 1);
        for (int yy = rlo; yy <= y + 1; yy++) {
            const int slot = (yy + 3) % 3;
            for (int i = tid; i < CIN * 130; i += 256) {
                const int c = i / 130, col = i % 130;
                const int gx = x0 + col - 1;
                float v = 0.f;
                if ((unsigned)yy < HH && (unsigned)gx < WW)
                    v = inb[(size_t)c * HW + (size_t)yy * WW + gx];
                in_u[c * CSTR + slot * ROWF + col] = f2tf32(v);
            }
        }
        __syncthreads();

        float acc[2][NSUB / 8][4];
        #pragma unroll
        for (int mt = 0; mt < 2; mt++)
            #pragma unroll
            for (int nt = 0; nt < NSUB / 8; nt++)
                #pragma unroll
                for (int e = 0; e < 4; e++) acc[mt][nt][e] = 0.f;

        #pragma unroll 1
        for (int tap = 0; tap < 9; tap++) {
            const int dy = tap / 3, dx = tap - dy * 3;
            const int slot = (y + dy + 2) % 3;
            const int abase = slot * ROWF + mbase + g + dx;  // smem col for pixel m: m+dx
            const int wbase = tap * CIN * NSTR + nbase;
            #pragma unroll
            for (int ks = 0; ks < NKS; ks++) {
                const int c0 = ks * 8 + tg;
                uint32_t a[2][4];
                #pragma unroll
                for (int mt = 0; mt < 2; mt++) {
                    const int base = c0 * CSTR + abase + mt * 16;
                    a[mt][0] = in_u[base];
                    a[mt][1] = in_u[base + 8];
                    a[mt][2] = in_u[base + 4 * CSTR];
                    a[mt][3] = in_u[base + 4 * CSTR + 8];
                }
                #pragma unroll
                for (int nt = 0; nt < NSUB / 8; nt++) {
                    const int wb = wbase + c0 * NSTR + nt * 8 + g;
                    const uint32_t b0 = w_u[wb];
                    const uint32_t b1 = w_u[wb + 4 * NSTR];
                    #pragma unroll
                    for (int mt = 0; mt < 2; mt++)
                        mma8(acc[mt][nt], a[mt], b0, b1);
                }
            }
        }

        // ---- epilogue ----
        #pragma unroll
        for (int mt = 0; mt < 2; mt++) {
            const int px = x0 + mbase + mt * 16 + g;
            #pragma unroll
            for (int nt = 0; nt < NSUB / 8; nt++) {
                #pragma unroll
                for (int e = 0; e < 4; e++) {
                    const int ch = nbase + nt * 8 + tg * 2 + (e & 1);
                    const int xp = px + (e >> 1) * 8;
                    if (!H3 || ch < 12) {
                        float bv;
                        if (H3) bv = (ch < 4 ? bA : (ch < 8 ? bB2 : bC))[ch & 3];
                        else bv = bA[ch];
                        float v = acc[mt][nt][e] + bv;
                        if (pr && v < 0.f) v *= alpha;
                        ob[(size_t)ch * HW + (size_t)y * WW + xp] = v;
                    }
                }
            }
        }
    }
}

// ================= scalar 3x3 conv (conv1: CIN=3) =================
template<int CIN, int CHUNK, int COUT>
__global__ __launch_bounds__(256) void conv3x3_k(
    const float* __restrict__ in, const float* __restrict__ wgt,
    const float* __restrict__ bias, const float* __restrict__ pr,
    float* __restrict__ out)
{
    constexpr int NCB = COUT / 4;
    __shared__ float s_in[CHUNK][18][66];
    __shared__ float s_w[4][CHUNK][9];

    const int tid = threadIdx.x;
    const int tx = tid & 31, ty = tid >> 5;
    const int bz = blockIdx.z;
    const int cb = bz % NCB, b = bz / NCB;
    const int obase = cb * 4;
    const int x0 = blockIdx.x * 64, y0 = blockIdx.y * 16;

    float acc[4][2][2] = {};

    for (int c0 = 0; c0 < CIN; c0 += CHUNK) {
        for (int i = tid; i < 4 * CHUNK * 9; i += 256) {
            int o = i / (CHUNK * 9);
            int r = i % (CHUNK * 9);
            int c = r / 9, t = r % 9;
            s_w[o][c][t] = wgt[((size_t)(obase + o) * CIN + c0 + c) * 9 + t];
        }
        for (int i = tid; i < CHUNK * 18 * 66; i += 256) {
            int c = i / (18 * 66);
            int r2 = i % (18 * 66);
            int rr = r2 / 66, cc = r2 % 66;
            int gy = y0 + rr - 1, gx = x0 + cc - 1;
            float v = 0.f;
            if ((unsigned)gy < HH && (unsigned)gx < WW)
                v = in[((size_t)(b * CIN + c0 + c)) * HW + (size_t)gy * WW + gx];
            s_in[c][rr][cc] = v;
        }
        __syncthreads();

        #pragma unroll
        for (int c = 0; c < CHUNK; c++) {
            float vL[4][3], vR[4][3];
            #pragma unroll
            for (int rr = 0; rr < 4; rr++)
                #pragma unroll
                for (int dx = 0; dx < 3; dx++) {
                    vL[rr][dx] = s_in[c][2 * ty + rr][tx + dx];
                    vR[rr][dx] = s_in[c][2 * ty + rr][tx + 32 + dx];
                }
            #pragma unroll
            for (int o = 0; o < 4; o++)
                #pragma unroll
                for (int dy = 0; dy < 3; dy++)
                    #pragma unroll
                    for (int dx = 0; dx < 3; dx++) {
                        float wv = s_w[o][c][dy * 3 + dx];
                        acc[o][0][0] += vL[dy][dx] * wv;
                        acc[o][1][0] += vL[dy + 1][dx] * wv;
                        acc[o][0][1] += vR[dy][dx] * wv;
                        acc[o][1][1] += vR[dy + 1][dx] * wv;
                    }
        }
        __syncthreads();
    }

    const float a = pr ? pr[0] : 0.f;
    #pragma unroll
    for (int o = 0; o < 4; o++) {
        float bo = bias[obase + o];
        #pragma unroll
        for (int py = 0; py < 2; py++) {
            int gy = y0 + 2 * ty + py;
            #pragma unroll
            for (int px = 0; px < 2; px++) {
                int gx = x0 + tx + px * 32;
                float v = acc[o][py][px] + bo;
                if (pr && v < 0.f) v *= a;
                out[((size_t)(b * COUT + obase + o)) * HW + (size_t)gy * WW + gx] = v;
            }
        }
    }
}

// ================= GAP over 12-channel head map =================
__global__ __launch_bounds__(256) void gap12_k(const float* __restrict__ hp, float* __restrict__ g)
{
    __shared__ float smr[256];
    const int bc = blockIdx.x;           // b*12 + c
    const int b = bc / 12, c = bc % 12;
    const float4* p = (const float4*)(hp + (size_t)bc * HW);
    float s = 0.f;
    for (int i = threadIdx.x; i < HW / 4; i += 256) {
        float4 v = p[i];
        s += (v.x + v.y) + (v.z + v.w);
    }
    smr[threadIdx.x] = s;
    __syncthreads();
    for (int st = 128; st > 0; st >>= 1) {
        if (threadIdx.x < st) smr[threadIdx.x] += smr[threadIdx.x + st];
        __syncthreads();
    }
    if (threadIdx.x == 0) g[(c >> 2) * 32 + b * 4 + (c & 3)] = smr[0] * (1.0f / HW);
}

__global__ void se_k(const float* __restrict__ g, const float* __restrict__ c1,
                     const float* __restrict__ c2, float* __restrict__ s)
{
    __shared__ float t[BB][4];
    int tid = threadIdx.x;
    if (tid < BB * 4) {
        int b = tid >> 2, c = tid & 3;
        float v = 0.f;
        #pragma unroll
        for (int k = 0; k < 4; k++) v += c1[c * 4 + k] * g[b * 4 + k];
        t[b][c] = fmaxf(v, 0.f);
    }
    __syncthreads();
    if (tid < BB * 4) {
        int b = tid >> 2, c = tid & 3;
        float v = 0.f;
        #pragma unroll
        for (int k = 0; k < 4; k++) v += c2[c * 4 + k] * t[b][k];
        s[b * 4 + c] = 1.f / (1.f + __expf(-v));
    }
}

__global__ __launch_bounds__(256) void hblur_k(const float* __restrict__ src,
                                               float* __restrict__ o5,
                                               float* __restrict__ o15,
                                               float* __restrict__ o25)
{
    __shared__ float row[280];
    const int bc = blockIdx.z;
    const int y = blockIdx.y;
    const int xs = blockIdx.x * 256;
    const size_t base = (size_t)bc * HW + (size_t)y * WW;
    for (int i = threadIdx.x; i < 280; i += 256) {
        int gx = xs + i - 12;
        row[i] = ((unsigned)gx < WW) ? src[base + gx] : 0.f;
    }
    __syncthreads();
    const int cx = threadIdx.x + 12;
    float s = row[cx - 2] + row[cx - 1] + row[cx] + row[cx + 1] + row[cx + 2];
    o5[base + xs + threadIdx.x] = s;
    #pragma unroll
    for (int d = 3; d <= 7; d++) s += row[cx - d] + row[cx + d];
    o15[base + xs + threadIdx.x] = s;
    #pragma unroll
    for (int d = 8; d <= 12; d++) s += row[cx - d] + row[cx + d];
    o25[base + xs + threadIdx.x] = s;
}

// fuse: softmax over 4 head channels (from 12-ch HPA at hoff) + vertical box + combine
__global__ __launch_bounds__(256) void fuse_k(
    const float* __restrict__ xin, const float* __restrict__ hp, int hoff,
    const float* __restrict__ sv,
    const float* __restrict__ b5, const float* __restrict__ b15, const float* __restrict__ b25,
    float* __restrict__ out)
{
    const int x = blockIdx.x * 32 + threadIdx.x;
    const int y = blockIdx.y * 8 + threadIdx.y;
    const int z = blockIdx.z;
    const int c = z % 3, b = z / 3;

    const size_t hbase = ((size_t)(b * 12 + hoff)) * HW + (size_t)y * WW + x;
    float e0 = hp[hbase] * sv[b * 4 + 0];
    float e1 = hp[hbase + (size_t)HW] * sv[b * 4 + 1];
    float e2 = hp[hbase + (size_t)2 * HW] * sv[b * 4 + 2];
    float e3 = hp[hbase + (size_t)3 * HW] * sv[b * 4 + 3];
    float m = fmaxf(fmaxf(e0, e1), fmaxf(e2, e3));
    float w0 = __expf(e0 - m), w1 = __expf(e1 - m), w2 = __expf(e2 - m), w3 = __expf(e3 - m);
    float inv = 1.f / (w0 + w1 + w2 + w3);

    const size_t cb = ((size_t)(b * 3 + c)) * HW;
    float v5 = 0.f, v15 = 0.f, v25 = 0.f;
    #pragma unroll
    for (int d = -12; d <= 12; d++) {
        int yy = y + d;
        if ((unsigned)yy < HH) {
            size_t idx = cb + (size_t)yy * WW + x;
            int ad = d < 0 ? -d : d;
            v25 += b25[idx];
            if (ad <= 7) v15 += b15[idx];
            if (ad <= 2) v5 += b5[idx];
        }
    }
    float o = (w0 * inv) * xin[cb + (size_t)y * WW + x]
            + (w1 * inv) * (v5 * (1.f / 25.f))
            + (w2 * inv) * (v15 * (1.f / 225.f))
            + (w3 * inv) * (v25 * (1.f / 625.f));
    out[cb + (size_t)y * WW + x] = o;
}

// ================= launch =================
extern "C" void kernel_launch(void* const* d_in, const int* in_sizes, int n_in,
                              void* d_out, int out_size)
{
    const float* x   = (const float*)d_in[0];
    const float* bw1 = (const float*)d_in[1];
    const float* bb1 = (const float*)d_in[2];
    const float* a1  = (const float*)d_in[3];
    const float* bw2 = (const float*)d_in[4];
    const float* bb2 = (const float*)d_in[5];
    const float* a2  = (const float*)d_in[6];
    const float* bw3 = (const float*)d_in[7];
    const float* bb3 = (const float*)d_in[8];
    const float* a3  = (const float*)d_in[9];
    const float* hw_[3]  = { (const float*)d_in[10], (const float*)d_in[14], (const float*)d_in[18] };
    const float* hb_[3]  = { (const float*)d_in[11], (const float*)d_in[15], (const float*)d_in[19] };
    const float* hc1_[3] = { (const float*)d_in[12], (const float*)d_in[16], (const float*)d_in[20] };
    const float* hc2_[3] = { (const float*)d_in[13], (const float*)d_in[17], (const float*)d_in[21] };

    float *B1, *B2, *G, *S, *HB5, *HB15, *HB25, *TX;
    cudaGetSymbolAddress((void**)&B1, g_B1);
    cudaGetSymbolAddress((void**)&B2, g_B2);
    cudaGetSymbolAddress((void**)&G, g_G);
    cudaGetSymbolAddress((void**)&S, g_S);
    cudaGetSymbolAddress((void**)&HB5, g_HB5);
    cudaGetSymbolAddress((void**)&HB15, g_HB15);
    cudaGetSymbolAddress((void**)&HB25, g_HB25);
    cudaGetSymbolAddress((void**)&TX, g_TX);

    // smem bytes: in tile + weight tile
    const int smem2 = (32 * 396 + 9 * 32 * 72) * 4;  // 133632
    const int smem3 = (64 * 396 + 9 * 64 * 40) * 4;  // 193536
    const int smemH = (32 * 396 + 9 * 32 * 24) * 4;  // 78336
    cudaFuncSetAttribute((const void*)mconv_k<32, 64, 32, 72, false>,
                         cudaFuncAttributeMaxDynamicSharedMemorySize, smem2);
    cudaFuncSetAttribute((const void*)mconv_k<64, 32, 16, 40, false>,
                         cudaFuncAttributeMaxDynamicSharedMemorySize, smem3);
    cudaFuncSetAttribute((const void*)mconv_k<32, 12, 8, 24, true>,
                         cudaFuncAttributeMaxDynamicSharedMemorySize, smemH);

    const dim3 tgrid(WW / 128, HH / 8, BB);

    // body
    conv3x3_k<3, 3, 32><<<dim3(8, 32, BB * 8), 256>>>(x, bw1, bb1, a1, B1);
    mconv_k<32, 64, 32, 72, false><<<tgrid, 256, smem2>>>(
        B1, bw2, nullptr, nullptr, bb2, nullptr, nullptr, a2, B2);
    mconv_k<64, 32, 16, 40, false><<<tgrid, 256, smem3>>>(
        B2, bw3, nullptr, nullptr, bb3, nullptr, nullptr, a3, B1);

    // heads fused (12 channels) -> reuse B2 as HPA
    float* HPA = B2;
    mconv_k<32, 12, 8, 24, true><<<tgrid, 256, smemH>>>(
        B1, hw_[0], hw_[1], hw_[2], hb_[0], hb_[1], hb_[2], nullptr, HPA);
    gap12_k<<<BB * 12, 256>>>(HPA, G);
    for (int i = 0; i < 3; i++)
        se_k<<<1, 32>>>(G + i * 32, hc1_[i], hc2_[i], S + i * 32);

    // fuse stages
    hblur_k<<<dim3(2, HH, BB * 3), 256>>>(x, HB5, HB15, HB25);
    fuse_k<<<dim3(16, 64, BB * 3), dim3(32, 8)>>>(x, HPA, 0, S + 0, HB5, HB15, HB25, TX);
    hblur_k<<<dim3(2, HH, BB * 3), 256>>>(TX, HB5, HB15, HB25);
    fuse_k<<<dim3(16, 64, BB * 3), dim3(32, 8)>>>(TX, HPA, 4, S + 32, HB5, HB15, HB25, TX);
    hblur_k<<<dim3(2, HH, BB * 3), 256>>>(TX, HB5, HB15, HB25);
    fuse_k<<<dim3(16, 64, BB * 3), dim3(32, 8)>>>(TX, HPA, 8, S + 64, HB5, HB15, HB25,
                                                  (float*)d_out);
    (void)in_sizes; (void)n_in; (void)out_size;
}

// round 4
// speedup vs baseline: 2.4358x; 1.1380x over previous
#include <cuda_runtime.h>
#include <cstdint>
#include <cstddef>

#define HH 512
#define WW 512
#define BB 8
constexpr int HW = HH * WW;

// ---------------- scratch ----------------
__device__ float g_B1[(size_t)BB * 64 * HW];
__device__ float g_B2[(size_t)BB * 64 * HW];   // reused as HPA (12ch head maps)
__device__ float g_G[3 * BB * 4];
__device__ float g_P[96 * 16];
__device__ float g_S[3 * BB * 4];
__device__ float g_TX[(size_t)BB * 3 * HW];
__device__ float g_TX2[(size_t)BB * 3 * HW];

// ---------------- helpers ----------------
__device__ __forceinline__ uint32_t f2tf32(float v) {
    uint32_t r;
    asm("cvt.rna.tf32.f32 %0, %1;" : "=r"(r) : "f"(v));
    return r;
}
__device__ __forceinline__ void mma8(float* d, uint32_t a0, uint32_t a1, uint32_t a2,
                                     uint32_t a3, uint32_t b0, uint32_t b1) {
    asm volatile(
        "mma.sync.aligned.m16n8k8.row.col.f32.tf32.tf32.f32 "
        "{%0,%1,%2,%3}, {%4,%5,%6,%7}, {%8,%9}, {%0,%1,%2,%3};"
        : "+f"(d[0]), "+f"(d[1]), "+f"(d[2]), "+f"(d[3])
        : "r"(a0), "r"(a1), "r"(a2), "r"(a3), "r"(b0), "r"(b1));
}

// ================= tensor-core 3x3 conv via mma.sync tf32 =================
// Block 256 threads (8 warps: 4 M-subtiles x 2 N-groups). Tile: 128 pixels x NTOT ch,
// iterated over 8 output rows. A: pixel-major, channels pair-permuted so fragment
// elements (k, k+4) are one float2 -> LDS.64. PSTR = CIN+8 (PSTR%32==8 -> conflict-free).
template<int CIN, int COUT, int NSUB, bool H3>
__global__ __launch_bounds__(256) void mconv_k(
    const float* __restrict__ in,
    const float* __restrict__ wA, const float* __restrict__ wB2, const float* __restrict__ wC,
    const float* __restrict__ bA, const float* __restrict__ bB2, const float* __restrict__ bC,
    const float* __restrict__ pr, float* __restrict__ out)
{
    constexpr int NTOT = 2 * NSUB;
    constexpr int PSTR = CIN + 8;      // floats per staged pixel
    constexpr int PSTR2 = PSTR / 2;
    constexpr int NKS = CIN / 8;

    extern __shared__ float sm[];
    float* a_f = sm;                               // 390 * PSTR floats
    float* w_f = sm + 390 * PSTR;                  // 9 * CIN * NTOT floats
    const float2* a2 = (const float2*)a_f;
    const float2* w2 = (const float2*)w_f;

    const int tid = threadIdx.x;
    const int lane = tid & 31;
    const int wid = tid >> 5;
    const int g = lane >> 2, tg = lane & 3;
    const int mbase = (wid >> 1) * 32;
    const int nbase = (wid & 1) * NSUB;
    const int x0 = blockIdx.x * 128;
    const int y0 = blockIdx.y * 8;
    const int b = blockIdx.z;
    const int outc = H3 ? 12 : COUT;

    // ---- stage all weights, pair-permuted: pair ((tap*NKS+ks)*NTOT+n)*4+tg holds (k=tg, k=tg+4)
    for (int i = tid; i < 9 * CIN * NTOT; i += 256) {
        const int tap = i / (CIN * NTOT);
        const int r = i % (CIN * NTOT);
        const int n = r / CIN, c = r % CIN;
        float v = 0.f;
        if (H3) {
            if (n < 12) {
                const float* wp = (n < 4) ? wA : (n < 8 ? wB2 : wC);
                v = wp[((size_t)(n & 3) * CIN + c) * 9 + tap];
            }
        } else if (n < COUT) {
            v = wA[((size_t)n * CIN + c) * 9 + tap];
        }
        const int pair = ((tap * NKS + (c >> 3)) * NTOT + n) * 4 + (c & 3);
        const int el = (c >> 2) & 1;
        w_f[pair * 2 + el] = __uint_as_float(f2tf32(v));
    }

    const float* inb = in + (size_t)b * CIN * HW;
    float* ob = out + (size_t)b * outc * HW;
    const float alpha = pr ? pr[0] : 0.f;

    #pragma unroll 1
    for (int yi = 0; yi < 8; yi++) {
        const int y = y0 + yi;
        __syncthreads();
        const int rlo = (yi == 0) ? (y - 1) : (y + 1);
        for (int yy = rlo; yy <= y + 1; yy++) {
            const int slot = (yy + 3) % 3;
            for (int i = tid; i < CIN * 130; i += 256) {
                const int c = i / 130, col = i % 130;
                const int gx = x0 + col - 1;
                float v = 0.f;
                if ((unsigned)yy < HH && (unsigned)gx < WW)
                    v = inb[(size_t)c * HW + (size_t)yy * WW + gx];
                const int foff = (c >> 3) * 8 + (c & 3) * 2 + ((c >> 2) & 1);
                a_f[(slot * 130 + col) * PSTR + foff] = __uint_as_float(f2tf32(v));
            }
        }
        __syncthreads();

        float acc[2][NSUB / 8][4];
        #pragma unroll
        for (int mt = 0; mt < 2; mt++)
            #pragma unroll
            for (int nt = 0; nt < NSUB / 8; nt++)
                #pragma unroll
                for (int e = 0; e < 4; e++) acc[mt][nt][e] = 0.f;

        #pragma unroll 1
        for (int tap = 0; tap < 9; tap++) {
            const int dy = tap / 3, dx = tap - dy * 3;
            const int slot = (y + dy + 2) % 3;
            const int p0 = slot * 130 + mbase + g + dx;
            #pragma unroll
            for (int ks = 0; ks < NKS; ks++) {
                float2 qa[2][2];
                #pragma unroll
                for (int mt = 0; mt < 2; mt++) {
                    qa[mt][0] = a2[(p0 + mt * 16) * PSTR2 + ks * 4 + tg];
                    qa[mt][1] = a2[(p0 + mt * 16 + 8) * PSTR2 + ks * 4 + tg];
                }
                #pragma unroll
                for (int nt = 0; nt < NSUB / 8; nt++) {
                    const float2 qw = w2[((tap * NKS + ks) * NTOT + nbase + nt * 8 + g) * 4 + tg];
                    const uint32_t b0 = __float_as_uint(qw.x);
                    const uint32_t b1 = __float_as_uint(qw.y);
                    #pragma unroll
                    for (int mt = 0; mt < 2; mt++)
                        mma8(acc[mt][nt],
                             __float_as_uint(qa[mt][0].x), __float_as_uint(qa[mt][1].x),
                             __float_as_uint(qa[mt][0].y), __float_as_uint(qa[mt][1].y),
                             b0, b1);
                }
            }
        }

        // ---- epilogue ----
        #pragma unroll
        for (int mt = 0; mt < 2; mt++) {
            const int px = x0 + mbase + mt * 16 + g;
            #pragma unroll
            for (int nt = 0; nt < NSUB / 8; nt++) {
                #pragma unroll
                for (int e = 0; e < 4; e++) {
                    const int ch = nbase + nt * 8 + tg * 2 + (e & 1);
                    const int xp = px + (e >> 1) * 8;
                    if (!H3 || ch < 12) {
                        float bv;
                        if (H3) bv = (ch < 4 ? bA : (ch < 8 ? bB2 : bC))[ch & 3];
                        else bv = bA[ch];
                        float v = acc[mt][nt][e] + bv;
                        if (pr && v < 0.f) v *= alpha;
                        ob[(size_t)ch * HW + (size_t)y * WW + xp] = v;
                    }
                }
            }
        }
    }
}

// ================= scalar 3x3 conv (conv1: CIN=3) =================
template<int CIN, int CHUNK, int COUT>
__global__ __launch_bounds__(256) void conv3x3_k(
    const float* __restrict__ in, const float* __restrict__ wgt,
    const float* __restrict__ bias, const float* __restrict__ pr,
    float* __restrict__ out)
{
    constexpr int NCB = COUT / 4;
    __shared__ float s_in[CHUNK][18][66];
    __shared__ float s_w[4][CHUNK][9];

    const int tid = threadIdx.x;
    const int tx = tid & 31, ty = tid >> 5;
    const int bz = blockIdx.z;
    const int cb = bz % NCB, b = bz / NCB;
    const int obase = cb * 4;
    const int x0 = blockIdx.x * 64, y0 = blockIdx.y * 16;

    float acc[4][2][2] = {};

    for (int c0 = 0; c0 < CIN; c0 += CHUNK) {
        for (int i = tid; i < 4 * CHUNK * 9; i += 256) {
            int o = i / (CHUNK * 9);
            int r = i % (CHUNK * 9);
            int c = r / 9, t = r % 9;
            s_w[o][c][t] = wgt[((size_t)(obase + o) * CIN + c0 + c) * 9 + t];
        }
        for (int i = tid; i < CHUNK * 18 * 66; i += 256) {
            int c = i / (18 * 66);
            int r2 = i % (18 * 66);
            int rr = r2 / 66, cc = r2 % 66;
            int gy = y0 + rr - 1, gx = x0 + cc - 1;
            float v = 0.f;
            if ((unsigned)gy < HH && (unsigned)gx < WW)
                v = in[((size_t)(b * CIN + c0 + c)) * HW + (size_t)gy * WW + gx];
            s_in[c][rr][cc] = v;
        }
        __syncthreads();

        #pragma unroll
        for (int c = 0; c < CHUNK; c++) {
            float vL[4][3], vR[4][3];
            #pragma unroll
            for (int rr = 0; rr < 4; rr++)
                #pragma unroll
                for (int dx = 0; dx < 3; dx++) {
                    vL[rr][dx] = s_in[c][2 * ty + rr][tx + dx];
                    vR[rr][dx] = s_in[c][2 * ty + rr][tx + 32 + dx];
                }
            #pragma unroll
            for (int o = 0; o < 4; o++)
                #pragma unroll
                for (int dy = 0; dy < 3; dy++)
                    #pragma unroll
                    for (int dx = 0; dx < 3; dx++) {
                        float wv = s_w[o][c][dy * 3 + dx];
                        acc[o][0][0] += vL[dy][dx] * wv;
                        acc[o][1][0] += vL[dy + 1][dx] * wv;
                        acc[o][0][1] += vR[dy][dx] * wv;
                        acc[o][1][1] += vR[dy + 1][dx] * wv;
                    }
        }
        __syncthreads();
    }

    const float a = pr ? pr[0] : 0.f;
    #pragma unroll
    for (int o = 0; o < 4; o++) {
        float bo = bias[obase + o];
        #pragma unroll
        for (int py = 0; py < 2; py++) {
            int gy = y0 + 2 * ty + py;
            #pragma unroll
            for (int px = 0; px < 2; px++) {
                int gx = x0 + tx + px * 32;
                float v = acc[o][py][px] + bo;
                if (pr && v < 0.f) v *= a;
                out[((size_t)(b * COUT + obase + o)) * HW + (size_t)gy * WW + gx] = v;
            }
        }
    }
}

// ================= parallel GAP: partials + combine =================
__global__ __launch_bounds__(256) void gapp_k(const float* __restrict__ hp, float* __restrict__ part)
{
    __shared__ float smr[256];
    const int bc = blockIdx.x, seg = blockIdx.y;
    const float4* p = (const float4*)(hp + (size_t)bc * HW + (size_t)seg * (HW / 16));
    float s = 0.f;
    for (int i = threadIdx.x; i < HW / 64; i += 256) {
        float4 v = p[i];
        s += (v.x + v.y) + (v.z + v.w);
    }
    smr[threadIdx.x] = s;
    __syncthreads();
    for (int st = 128; st > 0; st >>= 1) {
        if (threadIdx.x < st) smr[threadIdx.x] += smr[threadIdx.x + st];
        __syncthreads();
    }
    if (threadIdx.x == 0) part[bc * 16 + seg] = smr[0];
}

__global__ void gapc_k(const float* __restrict__ part, float* __restrict__ g)
{
    const int t = threadIdx.x;
    if (t < 96) {
        const int b = t / 12, c = t % 12;
        float s = 0.f;
        #pragma unroll
        for (int k = 0; k < 16; k++) s += part[t * 16 + k];
        g[(c >> 2) * 32 + b * 4 + (c & 3)] = s * (1.0f / HW);
    }
}

__global__ void se_k(const float* __restrict__ g, const float* __restrict__ c1,
                     const float* __restrict__ c2, float* __restrict__ s)
{
    __shared__ float t[BB][4];
    int tid = threadIdx.x;
    if (tid < BB * 4) {
        int b = tid >> 2, c = tid & 3;
        float v = 0.f;
        #pragma unroll
        for (int k = 0; k < 4; k++) v += c1[c * 4 + k] * g[b * 4 + k];
        t[b][c] = fmaxf(v, 0.f);
    }
    __syncthreads();
    if (tid < BB * 4) {
        int b = tid >> 2, c = tid & 3;
        float v = 0.f;
        #pragma unroll
        for (int k = 0; k < 4; k++) v += c2[c * 4 + k] * t[b][k];
        s[b * 4 + c] = 1.f / (1.f + __expf(-v));
    }
}

// ================= fused blur + softmax + combine =================
// box15 = box5 conv (3-tap stride 5), box25 = box5 conv (5-tap stride 5).
// Block: 32x8 threads -> 32x32 output tile. Thread handles 4 consecutive y via rolling sums.
__global__ __launch_bounds__(256) void blurfuse_k(
    const float* __restrict__ src, const float* __restrict__ hp, int hoff,
    const float* __restrict__ sv, float* __restrict__ out)
{
    __shared__ float s_src[56][57];
    __shared__ float s_h5[56][52];
    __shared__ float s_h15[56][32];
    __shared__ float s_h25[56][32];

    const int tid = threadIdx.y * 32 + threadIdx.x;
    const int tx = threadIdx.x, ty = threadIdx.y;
    const int x0 = blockIdx.x * 32, y0 = blockIdx.y * 32;
    const int z = blockIdx.z;
    const int c = z % 3, b = z / 3;
    const size_t cb = (size_t)(b * 3 + c) * HW;

    // stage src tile rows y0-12..y0+43, cols x0-12..x0+43 (zero-padded)
    for (int i = tid; i < 56 * 56; i += 256) {
        const int r = i / 56, cc = i % 56;
        const int gy = y0 - 12 + r, gx = x0 - 12 + cc;
        float v = 0.f;
        if ((unsigned)gy < HH && (unsigned)gx < WW)
            v = src[cb + (size_t)gy * WW + gx];
        s_src[r][cc] = v;
    }
    __syncthreads();

    // h5: col j corresponds to x = x0-10+j, from src cols j..j+4
    for (int i = tid; i < 56 * 52; i += 256) {
        const int r = i / 52, j = i % 52;
        s_h5[r][j] = s_src[r][j] + s_src[r][j + 1] + s_src[r][j + 2]
                   + s_src[r][j + 3] + s_src[r][j + 4];
    }
    __syncthreads();

    // h15/h25 at the 32 output cols
    for (int i = tid; i < 56 * 32; i += 256) {
        const int r = i / 32, t = i % 32;
        const float h15 = s_h5[r][t + 5] + s_h5[r][t + 10] + s_h5[r][t + 15];
        s_h15[r][t] = h15;
        s_h25[r][t] = h15 + s_h5[r][t] + s_h5[r][t + 20];
    }
    __syncthreads();

    // vertical rolling sums; thread covers y = y0 + ty*4 + j, j=0..3
    const int r0 = ty * 4 + 12;
    float v5 = 0.f, v15 = 0.f, v25 = 0.f;
    #pragma unroll
    for (int d = -2; d <= 2; d++) v5 += s_h5[r0 + d][tx + 10];
    #pragma unroll
    for (int d = -7; d <= 7; d++) v15 += s_h15[r0 + d][tx];
    #pragma unroll
    for (int d = -12; d <= 12; d++) v25 += s_h25[r0 + d][tx];

    const float s0 = sv[b * 4 + 0], s1 = sv[b * 4 + 1], s2 = sv[b * 4 + 2], s3 = sv[b * 4 + 3];
    const int x = x0 + tx;

    #pragma unroll
    for (int j = 0; j < 4; j++) {
        const int y = y0 + ty * 4 + j;
        const int r = r0 + j;
        const size_t hbase = ((size_t)(b * 12 + hoff)) * HW + (size_t)y * WW + x;
        float e0 = hp[hbase] * s0;
        float e1 = hp[hbase + (size_t)HW] * s1;
        float e2 = hp[hbase + (size_t)2 * HW] * s2;
        float e3 = hp[hbase + (size_t)3 * HW] * s3;
        float m = fmaxf(fmaxf(e0, e1), fmaxf(e2, e3));
        float w0 = __expf(e0 - m), w1 = __expf(e1 - m), w2 = __expf(e2 - m), w3 = __expf(e3 - m);
        float inv = 1.f / (w0 + w1 + w2 + w3);
        float o = (w0 * inv) * s_src[r][tx + 12]
                + (w1 * inv) * (v5 * (1.f / 25.f))
                + (w2 * inv) * (v15 * (1.f / 225.f))
                + (w3 * inv) * (v25 * (1.f / 625.f));
        out[cb + (size_t)y * WW + x] = o;
        if (j < 3) {
            v5 += s_h5[r + 3][tx + 10] - s_h5[r - 2][tx + 10];
            v15 += s_h15[r + 8][tx] - s_h15[r - 7][tx];
            v25 += s_h25[r + 13][tx] - s_h25[r - 12][tx];
        }
    }
}

// ================= launch =================
extern "C" void kernel_launch(void* const* d_in, const int* in_sizes, int n_in,
                              void* d_out, int out_size)
{
    const float* x   = (const float*)d_in[0];
    const float* bw1 = (const float*)d_in[1];
    const float* bb1 = (const float*)d_in[2];
    const float* a1  = (const float*)d_in[3];
    const float* bw2 = (const float*)d_in[4];
    const float* bb2 = (const float*)d_in[5];
    const float* a2  = (const float*)d_in[6];
    const float* bw3 = (const float*)d_in[7];
    const float* bb3 = (const float*)d_in[8];
    const float* a3  = (const float*)d_in[9];
    const float* hw_[3]  = { (const float*)d_in[10], (const float*)d_in[14], (const float*)d_in[18] };
    const float* hb_[3]  = { (const float*)d_in[11], (const float*)d_in[15], (const float*)d_in[19] };
    const float* hc1_[3] = { (const float*)d_in[12], (const float*)d_in[16], (const float*)d_in[20] };
    const float* hc2_[3] = { (const float*)d_in[13], (const float*)d_in[17], (const float*)d_in[21] };

    float *B1, *B2, *G, *P, *S, *TX, *TX2;
    cudaGetSymbolAddress((void**)&B1, g_B1);
    cudaGetSymbolAddress((void**)&B2, g_B2);
    cudaGetSymbolAddress((void**)&G, g_G);
    cudaGetSymbolAddress((void**)&P, g_P);
    cudaGetSymbolAddress((void**)&S, g_S);
    cudaGetSymbolAddress((void**)&TX, g_TX);
    cudaGetSymbolAddress((void**)&TX2, g_TX2);

    // smem: A = 390*PSTR floats, W = 9*CIN*NTOT floats
    const int smem2 = (390 * 40 + 9 * 32 * 64) * 4;  // 136128
    const int smem3 = (390 * 72 + 9 * 64 * 32) * 4;  // 186048
    const int smemH = (390 * 40 + 9 * 32 * 16) * 4;  // 80832
    cudaFuncSetAttribute((const void*)mconv_k<32, 64, 32, false>,
                         cudaFuncAttributeMaxDynamicSharedMemorySize, smem2);
    cudaFuncSetAttribute((const void*)mconv_k<64, 32, 16, false>,
                         cudaFuncAttributeMaxDynamicSharedMemorySize, smem3);
    cudaFuncSetAttribute((const void*)mconv_k<32, 12, 8, true>,
                         cudaFuncAttributeMaxDynamicSharedMemorySize, smemH);

    const dim3 tgrid(WW / 128, HH / 8, BB);

    // body
    conv3x3_k<3, 3, 32><<<dim3(8, 32, BB * 8), 256>>>(x, bw1, bb1, a1, B1);
    mconv_k<32, 64, 32, false><<<tgrid, 256, smem2>>>(
        B1, bw2, nullptr, nullptr, bb2, nullptr, nullptr, a2, B2);
    mconv_k<64, 32, 16, false><<<tgrid, 256, smem3>>>(
        B2, bw3, nullptr, nullptr, bb3, nullptr, nullptr, a3, B1);

    // heads fused (12 channels) -> reuse B2 as HPA
    float* HPA = B2;
    mconv_k<32, 12, 8, true><<<tgrid, 256, smemH>>>(
        B1, hw_[0], hw_[1], hw_[2], hb_[0], hb_[1], hb_[2], nullptr, HPA);
    gapp_k<<<dim3(96, 16), 256>>>(HPA, P);
    gapc_k<<<1, 128>>>(P, G);
    for (int i = 0; i < 3; i++)
        se_k<<<1, 32>>>(G + i * 32, hc1_[i], hc2_[i], S + i * 32);

    // fused blur+softmax+combine stages (ping-pong; halo reads forbid in-place)
    const dim3 fgrid(16, 16, BB * 3);
    const dim3 fblk(32, 8);
    blurfuse_k<<<fgrid, fblk>>>(x,   HPA, 0, S + 0,  TX);
    blurfuse_k<<<fgrid, fblk>>>(TX,  HPA, 4, S + 32, TX2);
    blurfuse_k<<<fgrid, fblk>>>(TX2, HPA, 8, S + 64, (float*)d_out);
    (void)in_sizes; (void)n_in; (void)out_size;
}

// round 5
// speedup vs baseline: 3.6859x; 1.5132x over previous
#include <cuda_runtime.h>
#include <cstdint>
#include <cstddef>

#define HH 512
#define WW 512
#define BB 8
constexpr int HW = HH * WW;

// ---------------- scratch ----------------
// B1: NHWC-permuted 32ch  [b][pixel][32]
// B2: NHWC-permuted 64ch  [b][pixel][64]; reused as HPA [b][pixel][16]
__device__ float g_B1[(size_t)BB * HW * 32];
__device__ float g_B2[(size_t)BB * HW * 64];
__device__ float g_G[3 * BB * 4];
__device__ float g_P[BB * 16 * 12];
__device__ float g_S[3 * BB * 4];
__device__ float g_TX[(size_t)BB * 3 * HW];
__device__ float g_TX2[(size_t)BB * 3 * HW];

// ---------------- helpers ----------------
__device__ __forceinline__ constexpr int foff(int c) {
    // pair-permuted channel position: (c, c+4) adjacent within each group of 8
    return (c >> 3) * 8 + (c & 3) * 2 + ((c >> 2) & 1);
}
__device__ __forceinline__ uint32_t f2tf32(float v) {
    uint32_t r;
    asm("cvt.rna.tf32.f32 %0, %1;" : "=r"(r) : "f"(v));
    return r;
}
__device__ __forceinline__ uint32_t smem_u32(const void* p) {
    uint32_t r;
    asm("{ .reg .u64 t; cvta.to.shared.u64 t, %1; cvt.u32.u64 %0, t; }" : "=r"(r) : "l"(p));
    return r;
}
__device__ __forceinline__ void mma8(float* d, uint32_t a0, uint32_t a1, uint32_t a2,
                                     uint32_t a3, uint32_t b0, uint32_t b1) {
    asm volatile(
        "mma.sync.aligned.m16n8k8.row.col.f32.tf32.tf32.f32 "
        "{%0,%1,%2,%3}, {%4,%5,%6,%7}, {%8,%9}, {%0,%1,%2,%3};"
        : "+f"(d[0]), "+f"(d[1]), "+f"(d[2]), "+f"(d[3])
        : "r"(a0), "r"(a1), "r"(a2), "r"(a3), "r"(b0), "r"(b1));
}
#define CP_A16(dst, src) asm volatile("cp.async.ca.shared.global [%0], [%1], 16;" :: "r"(dst), "l"(src) : "memory")
#define CP_COMMIT()      asm volatile("cp.async.commit_group;" ::: "memory")
#define CP_WAIT0()       asm volatile("cp.async.wait_group 0;" ::: "memory")
#define STZ16(dst)       asm volatile("st.shared.v4.b32 [%0], {%1,%1,%1,%1};" :: "r"(dst), "r"(0u) : "memory")

// ================= tensor-core 3x3 conv (NHWC in/out, cp.async pipelined) =================
// Block 256 threads (8 warps: 4 M-subtiles x 2 N-groups). 128 pixels x NTOT ch, 8 rows/block.
// A staged raw fp32 via cp.async (tf32 MMA truncates); 4 row slots, prefetch depth 1.
template<int CIN, int NSUB, bool H3>
__global__ __launch_bounds__(256) void mconv_k(
    const float* __restrict__ in,
    const float* __restrict__ wA, const float* __restrict__ wB2, const float* __restrict__ wC,
    const float* __restrict__ bA, const float* __restrict__ bB2, const float* __restrict__ bC,
    const float* __restrict__ pr, float* __restrict__ out)
{
    constexpr int NTOT = 2 * NSUB;
    constexpr int PSTR = CIN + 8;
    constexpr int PSTR2 = PSTR / 2;
    constexpr int NKS = CIN / 8;
    constexpr int SEGS = CIN / 4;               // 16B segments per pixel
    constexpr int LSEG = (CIN == 64) ? 4 : 3;   // log2(SEGS)
    constexpr int OSTR = H3 ? 16 : NTOT;        // output floats per pixel

    extern __shared__ float sm[];
    float* a_f = sm;                            // 4 slots * 130 * PSTR
    float* w_f = sm + 4 * 130 * PSTR;           // 9 * CIN * NTOT
    const float2* a2 = (const float2*)a_f;
    const float2* w2 = (const float2*)w_f;
    const uint32_t a_u = smem_u32(a_f);

    const int tid = threadIdx.x;
    const int lane = tid & 31;
    const int wid = tid >> 5;
    const int g = lane >> 2, tg = lane & 3;
    const int mbase = (wid >> 1) * 32;
    const int nbase = (wid & 1) * NSUB;
    const int x0 = blockIdx.x * 128;
    const int y0 = blockIdx.y * 8;
    const int b = blockIdx.z;

    // ---- weights: pair-permuted for B fragments (validated layout) ----
    for (int i = tid; i < 9 * CIN * NTOT; i += 256) {
        const int tap = i / (CIN * NTOT);
        const int r = i % (CIN * NTOT);
        const int n = r / CIN, c = r % CIN;
        float v = 0.f;
        if (H3) {
            if (n < 12) {
                const float* wp = (n < 4) ? wA : (n < 8 ? wB2 : wC);
                v = wp[((size_t)(n & 3) * CIN + c) * 9 + tap];
            }
        } else {
            v = wA[((size_t)n * CIN + c) * 9 + tap];
        }
        const int pair = ((tap * NKS + (c >> 3)) * NTOT + n) * 4 + (c & 3);
        w_f[pair * 2 + ((c >> 2) & 1)] = __uint_as_float(f2tf32(v));
    }

    const float* inb = in + (size_t)b * HW * CIN;

    // ---- row staging via cp.async (NHWC: row is contiguous) ----
    auto stage = [&](int yy) {
        const int slot = (yy + 4) & 3;
        const uint32_t sbase = a_u + (uint32_t)(slot * 130 * PSTR * 4);
        const bool rok = ((unsigned)yy < HH);
        const float* rowp = inb + (size_t)yy * WW * CIN;
        for (int i = tid; i < 130 * SEGS; i += 256) {
            const int p = i >> LSEG;
            const int s = i & (SEGS - 1);
            const int gx = x0 + p - 1;
            const uint32_t dst = sbase + (uint32_t)(p * PSTR * 4 + s * 16);
            if (rok && (unsigned)gx < WW)
                CP_A16(dst, rowp + (size_t)gx * CIN + s * 4);
            else
                STZ16(dst);
        }
    };

    stage(y0 - 1); stage(y0); stage(y0 + 1);
    CP_COMMIT();

    float* ob = out + (size_t)b * HW * OSTR;
    const float alpha = pr ? pr[0] : 0.f;

    #pragma unroll 1
    for (int yi = 0; yi < 8; yi++) {
        const int y = y0 + yi;
        CP_WAIT0();
        __syncthreads();
        if (yi < 7) { stage(y + 2); CP_COMMIT(); }

        float acc[2][NSUB / 8][4];
        #pragma unroll
        for (int mt = 0; mt < 2; mt++)
            #pragma unroll
            for (int nt = 0; nt < NSUB / 8; nt++)
                #pragma unroll
                for (int e = 0; e < 4; e++) acc[mt][nt][e] = 0.f;

        #pragma unroll 1
        for (int tap = 0; tap < 9; tap++) {
            const int dy = tap / 3, dx = tap - dy * 3;
            const int slot = (y + dy + 3) & 3;
            const int p0 = slot * 130 + mbase + g + dx;
            #pragma unroll
            for (int ks = 0; ks < NKS; ks++) {
                float2 qa[2][2];
                #pragma unroll
                for (int mt = 0; mt < 2; mt++) {
                    qa[mt][0] = a2[(p0 + mt * 16) * PSTR2 + ks * 4 + tg];
                    qa[mt][1] = a2[(p0 + mt * 16 + 8) * PSTR2 + ks * 4 + tg];
                }
                #pragma unroll
                for (int nt = 0; nt < NSUB / 8; nt++) {
                    const float2 qw = w2[((tap * NKS + ks) * NTOT + nbase + nt * 8 + g) * 4 + tg];
                    #pragma unroll
                    for (int mt = 0; mt < 2; mt++)
                        mma8(acc[mt][nt],
                             __float_as_uint(qa[mt][0].x), __float_as_uint(qa[mt][1].x),
                             __float_as_uint(qa[mt][0].y), __float_as_uint(qa[mt][1].y),
                             __float_as_uint(qw.x), __float_as_uint(qw.y));
                }
            }
        }

        // ---- epilogue (NHWC writes) ----
        #pragma unroll
        for (int mt = 0; mt < 2; mt++) {
            const int px = x0 + mbase + mt * 16 + g;
            #pragma unroll
            for (int nt = 0; nt < NSUB / 8; nt++) {
                #pragma unroll
                for (int e = 0; e < 4; e++) {
                    const int ch = nbase + nt * 8 + tg * 2 + (e & 1);
                    const int xp = px + (e >> 1) * 8;
                    if (!H3 || ch < 12) {
                        float bv;
                        if (H3) bv = (ch < 4 ? bA : (ch < 8 ? bB2 : bC))[ch & 3];
                        else bv = bA[ch];
                        float v = acc[mt][nt][e] + bv;
                        if (pr && v < 0.f) v *= alpha;
                        const int cpos = H3 ? ch : foff(ch);
                        ob[((size_t)y * WW + xp) * OSTR + cpos] = v;
                    }
                }
            }
        }
    }
}

// ================= conv1: 3->32, scalar, NHWC-permuted output =================
__global__ __launch_bounds__(256) void conv1_k(
    const float* __restrict__ x, const float* __restrict__ w,
    const float* __restrict__ bias, const float* __restrict__ pr,
    float* __restrict__ out)
{
    __shared__ float s_in[3][10][34];
    __shared__ float4 s_w4[27][8];
    __shared__ float s_b[32];

    const int tid = threadIdx.x;
    const int tx = tid & 31, ty = tid >> 5;
    const int x0 = blockIdx.x * 32, y0 = blockIdx.y * 8;
    const int b = blockIdx.z;

    for (int i = tid; i < 864; i += 256) {
        const int o = i / 27, t = i % 27;
        ((float*)s_w4)[t * 32 + o] = w[o * 27 + t];
    }
    if (tid < 32) s_b[tid] = bias[tid];
    for (int i = tid; i < 1020; i += 256) {
        const int c = i / 340, r = i % 340;
        const int rr = r / 34, cc = r % 34;
        const int gy = y0 - 1 + rr, gx = x0 - 1 + cc;
        float v = 0.f;
        if ((unsigned)gy < HH && (unsigned)gx < WW)
            v = x[((size_t)(b * 3 + c)) * HW + (size_t)gy * WW + gx];
        s_in[c][rr][cc] = v;
    }
    __syncthreads();

    float vin[27];
    #pragma unroll
    for (int c = 0; c < 3; c++)
        #pragma unroll
        for (int dy = 0; dy < 3; dy++)
            #pragma unroll
            for (int dx = 0; dx < 3; dx++)
                vin[c * 9 + dy * 3 + dx] = s_in[c][ty + dy][tx + dx];

    float acc[32];
    #pragma unroll
    for (int o = 0; o < 32; o++) acc[o] = 0.f;
    #pragma unroll
    for (int t = 0; t < 27; t++) {
        const float v = vin[t];
        #pragma unroll
        for (int og = 0; og < 8; og++) {
            const float4 wv = s_w4[t][og];
            acc[og * 4 + 0] += v * wv.x;
            acc[og * 4 + 1] += v * wv.y;
            acc[og * 4 + 2] += v * wv.z;
            acc[og * 4 + 3] += v * wv.w;
        }
    }

    const float alpha = pr[0];
    float of[32];
    #pragma unroll
    for (int o = 0; o < 32; o++) {
        float v = acc[o] + s_b[o];
        if (v < 0.f) v *= alpha;
        of[foff(o)] = v;
    }
    float* dst = out + ((size_t)b * HW + (size_t)(y0 + ty) * WW + x0 + tx) * 32;
    #pragma unroll
    for (int j = 0; j < 8; j++)
        ((float4*)dst)[j] = make_float4(of[4 * j], of[4 * j + 1], of[4 * j + 2], of[4 * j + 3]);
}

// ================= GAP over NHWC16 head maps =================
__global__ __launch_bounds__(256) void gapp_k(const float* __restrict__ hp, float* __restrict__ part)
{
    __shared__ float red[8][12];
    const int b = blockIdx.x, seg = blockIdx.y;
    const int tid = threadIdx.x;
    const float* base = hp + ((size_t)b * HW + (size_t)seg * (HW / 16)) * 16;
    float s[12];
    #pragma unroll
    for (int c = 0; c < 12; c++) s[c] = 0.f;
    for (int i = tid; i < HW / 16; i += 256) {
        const float4* q = (const float4*)(base + (size_t)i * 16);
        const float4 A = q[0], B4 = q[1], C = q[2];
        s[0] += A.x;  s[1] += A.y;  s[2] += A.z;  s[3] += A.w;
        s[4] += B4.x; s[5] += B4.y; s[6] += B4.z; s[7] += B4.w;
        s[8] += C.x;  s[9] += C.y;  s[10] += C.z; s[11] += C.w;
    }
    #pragma unroll
    for (int k = 16; k > 0; k >>= 1)
        #pragma unroll
        for (int c = 0; c < 12; c++) s[c] += __shfl_xor_sync(0xffffffffu, s[c], k);
    if ((tid & 31) == 0)
        #pragma unroll
        for (int c = 0; c < 12; c++) red[tid >> 5][c] = s[c];
    __syncthreads();
    if (tid < 12) {
        float t = 0.f;
        #pragma unroll
        for (int wdx = 0; wdx < 8; wdx++) t += red[wdx][tid];
        part[((size_t)b * 16 + seg) * 12 + tid] = t;
    }
}

__global__ void gapc_k(const float* __restrict__ part, float* __restrict__ g)
{
    const int t = threadIdx.x;
    if (t < 96) {
        const int b = t / 12, c = t % 12;
        float s = 0.f;
        #pragma unroll
        for (int k = 0; k < 16; k++) s += part[((size_t)b * 16 + k) * 12 + c];
        g[(c >> 2) * 32 + b * 4 + (c & 3)] = s * (1.0f / HW);
    }
}

__global__ void se_k(const float* __restrict__ g, const float* __restrict__ c1,
                     const float* __restrict__ c2, float* __restrict__ s)
{
    __shared__ float t[BB][4];
    int tid = threadIdx.x;
    if (tid < BB * 4) {
        int b = tid >> 2, c = tid & 3;
        float v = 0.f;
        #pragma unroll
        for (int k = 0; k < 4; k++) v += c1[c * 4 + k] * g[b * 4 + k];
        t[b][c] = fmaxf(v, 0.f);
    }
    __syncthreads();
    if (tid < BB * 4) {
        int b = tid >> 2, c = tid & 3;
        float v = 0.f;
        #pragma unroll
        for (int k = 0; k < 4; k++) v += c2[c * 4 + k] * t[b][k];
        s[b * 4 + c] = 1.f / (1.f + __expf(-v));
    }
}

// ================= fused blur + softmax + combine (hp is NHWC16) =================
__global__ __launch_bounds__(256) void blurfuse_k(
    const float* __restrict__ src, const float* __restrict__ hp, int hoff,
    const float* __restrict__ sv, float* __restrict__ out)
{
    __shared__ float s_src[56][57];
    __shared__ float s_h5[56][52];
    __shared__ float s_h15[56][32];
    __shared__ float s_h25[56][32];

    const int tid = threadIdx.y * 32 + threadIdx.x;
    const int tx = threadIdx.x, ty = threadIdx.y;
    const int x0 = blockIdx.x * 32, y0 = blockIdx.y * 32;
    const int z = blockIdx.z;
    const int c = z % 3, b = z / 3;
    const size_t cb = (size_t)(b * 3 + c) * HW;

    for (int i = tid; i < 56 * 56; i += 256) {
        const int r = i / 56, cc = i % 56;
        const int gy = y0 - 12 + r, gx = x0 - 12 + cc;
        float v = 0.f;
        if ((unsigned)gy < HH && (unsigned)gx < WW)
            v = src[cb + (size_t)gy * WW + gx];
        s_src[r][cc] = v;
    }
    __syncthreads();

    for (int i = tid; i < 56 * 52; i += 256) {
        const int r = i / 52, j = i % 52;
        s_h5[r][j] = s_src[r][j] + s_src[r][j + 1] + s_src[r][j + 2]
                   + s_src[r][j + 3] + s_src[r][j + 4];
    }
    __syncthreads();

    for (int i = tid; i < 56 * 32; i += 256) {
        const int r = i / 32, t = i % 32;
        const float h15 = s_h5[r][t + 5] + s_h5[r][t + 10] + s_h5[r][t + 15];
        s_h15[r][t] = h15;
        s_h25[r][t] = h15 + s_h5[r][t] + s_h5[r][t + 20];
    }
    __syncthreads();

    const int r0 = ty * 4 + 12;
    float v5 = 0.f, v15 = 0.f, v25 = 0.f;
    #pragma unroll
    for (int d = -2; d <= 2; d++) v5 += s_h5[r0 + d][tx + 10];
    #pragma unroll
    for (int d = -7; d <= 7; d++) v15 += s_h15[r0 + d][tx];
    #pragma unroll
    for (int d = -12; d <= 12; d++) v25 += s_h25[r0 + d][tx];

    const float s0 = sv[b * 4 + 0], s1 = sv[b * 4 + 1], s2 = sv[b * 4 + 2], s3 = sv[b * 4 + 3];
    const int x = x0 + tx;

    #pragma unroll
    for (int j = 0; j < 4; j++) {
        const int y = y0 + ty * 4 + j;
        const int r = r0 + j;
        const float4 hv = *(const float4*)(hp + ((size_t)b * HW + (size_t)y * WW + x) * 16 + hoff);
        float e0 = hv.x * s0, e1 = hv.y * s1, e2 = hv.z * s2, e3 = hv.w * s3;
        float m = fmaxf(fmaxf(e0, e1), fmaxf(e2, e3));
        float w0 = __expf(e0 - m), w1 = __expf(e1 - m), w2 = __expf(e2 - m), w3 = __expf(e3 - m);
        float inv = 1.f / (w0 + w1 + w2 + w3);
        float o = (w0 * inv) * s_src[r][tx + 12]
                + (w1 * inv) * (v5 * (1.f / 25.f))
                + (w2 * inv) * (v15 * (1.f / 225.f))
                + (w3 * inv) * (v25 * (1.f / 625.f));
        out[cb + (size_t)y * WW + x] = o;
        if (j < 3) {
            v5 += s_h5[r + 3][tx + 10] - s_h5[r - 2][tx + 10];
            v15 += s_h15[r + 8][tx] - s_h15[r - 7][tx];
            v25 += s_h25[r + 13][tx] - s_h25[r - 12][tx];
        }
    }
}

// ================= launch =================
extern "C" void kernel_launch(void* const* d_in, const int* in_sizes, int n_in,
                              void* d_out, int out_size)
{
    const float* x   = (const float*)d_in[0];
    const float* bw1 = (const float*)d_in[1];
    const float* bb1 = (const float*)d_in[2];
    const float* a1  = (const float*)d_in[3];
    const float* bw2 = (const float*)d_in[4];
    const float* bb2 = (const float*)d_in[5];
    const float* a2  = (const float*)d_in[6];
    const float* bw3 = (const float*)d_in[7];
    const float* bb3 = (const float*)d_in[8];
    const float* a3  = (const float*)d_in[9];
    const float* hw_[3]  = { (const float*)d_in[10], (const float*)d_in[14], (const float*)d_in[18] };
    const float* hb_[3]  = { (const float*)d_in[11], (const float*)d_in[15], (const float*)d_in[19] };
    const float* hc1_[3] = { (const float*)d_in[12], (const float*)d_in[16], (const float*)d_in[20] };
    const float* hc2_[3] = { (const float*)d_in[13], (const float*)d_in[17], (const float*)d_in[21] };

    float *B1, *B2, *G, *P, *S, *TX, *TX2;
    cudaGetSymbolAddress((void**)&B1, g_B1);
    cudaGetSymbolAddress((void**)&B2, g_B2);
    cudaGetSymbolAddress((void**)&G, g_G);
    cudaGetSymbolAddress((void**)&P, g_P);
    cudaGetSymbolAddress((void**)&S, g_S);
    cudaGetSymbolAddress((void**)&TX, g_TX);
    cudaGetSymbolAddress((void**)&TX2, g_TX2);

    // smem: 4*130*PSTR + 9*CIN*NTOT floats
    const int smem2 = (4 * 130 * 40 + 9 * 32 * 64) * 4;  // 156928
    const int smem3 = (4 * 130 * 72 + 9 * 64 * 32) * 4;  // 223488
    const int smemH = (4 * 130 * 40 + 9 * 32 * 16) * 4;  // 101632
    cudaFuncSetAttribute((const void*)mconv_k<32, 32, false>,
                         cudaFuncAttributeMaxDynamicSharedMemorySize, smem2);
    cudaFuncSetAttribute((const void*)mconv_k<64, 16, false>,
                         cudaFuncAttributeMaxDynamicSharedMemorySize, smem3);
    cudaFuncSetAttribute((const void*)mconv_k<32, 8, true>,
                         cudaFuncAttributeMaxDynamicSharedMemorySize, smemH);

    const dim3 tgrid(WW / 128, HH / 8, BB);

    // body
    conv1_k<<<dim3(16, 64, BB), 256>>>(x, bw1, bb1, a1, B1);
    mconv_k<32, 32, false><<<tgrid, 256, smem2>>>(
        B1, bw2, nullptr, nullptr, bb2, nullptr, nullptr, a2, B2);
    mconv_k<64, 16, false><<<tgrid, 256, smem3>>>(
        B2, bw3, nullptr, nullptr, bb3, nullptr, nullptr, a3, B1);

    // heads fused (NHWC16) -> reuse B2 as HPA
    float* HPA = B2;
    mconv_k<32, 8, true><<<tgrid, 256, smemH>>>(
        B1, hw_[0], hw_[1], hw_[2], hb_[0], hb_[1], hb_[2], nullptr, HPA);
    gapp_k<<<dim3(BB, 16), 256>>>(HPA, P);
    gapc_k<<<1, 128>>>(P, G);
    for (int i = 0; i < 3; i++)
        se_k<<<1, 32>>>(G + i * 32, hc1_[i], hc2_[i], S + i * 32);

    // fused blur+softmax+combine (ping-pong)
    const dim3 fgrid(16, 16, BB * 3);
    const dim3 fblk(32, 8);
    blurfuse_k<<<fgrid, fblk>>>(x,   HPA, 0, S + 0,  TX);
    blurfuse_k<<<fgrid, fblk>>>(TX,  HPA, 4, S + 32, TX2);
    blurfuse_k<<<fgrid, fblk>>>(TX2, HPA, 8, S + 64, (float*)d_out);
    (void)in_sizes; (void)n_in; (void)out_size;
}

// round 6
// speedup vs baseline: 6.0817x; 1.6500x over previous
#include <cuda_runtime.h>
#include <cuda_fp16.h>
#include <cstdint>
#include <cstddef>

#define HH 512
#define WW 512
#define BB 8
constexpr int HW = HH * WW;

// ---------------- scratch ----------------
// B1: fp16 NHWC-permuted 32ch; B2: fp16 NHWC-permuted 64ch, reused as fp32 HPA [pixel][16]
__device__ float g_B1[(size_t)BB * HW * 32 / 2];
__device__ float g_B2[(size_t)BB * HW * 64];
__device__ float g_G[3 * BB * 4];
__device__ float g_P[BB * 16 * 12];
__device__ float g_S[3 * BB * 4];
__device__ float g_TX[(size_t)BB * 3 * HW];
__device__ float g_TX2[(size_t)BB * 3 * HW];

// ---------------- helpers ----------------
__device__ __forceinline__ uint32_t smem_u32(const void* p) {
    uint32_t r;
    asm("{ .reg .u64 t; cvta.to.shared.u64 t, %1; cvt.u32.u64 %0, t; }" : "=r"(r) : "l"(p));
    return r;
}
__device__ __forceinline__ uint32_t pack_h2(float a, float b) {
    __half2 h = __floats2half2_rn(a, b);
    return *(uint32_t*)&h;
}
// fp16 m16n8k16 row.col, fp32 accumulate
__device__ __forceinline__ void mma16(float* d, uint32_t a0, uint32_t a1, uint32_t a2,
                                      uint32_t a3, uint32_t b0, uint32_t b1) {
    asm volatile(
        "mma.sync.aligned.m16n8k16.row.col.f32.f16.f16.f32 "
        "{%0,%1,%2,%3}, {%4,%5,%6,%7}, {%8,%9}, {%0,%1,%2,%3};"
        : "+f"(d[0]), "+f"(d[1]), "+f"(d[2]), "+f"(d[3])
        : "r"(a0), "r"(a1), "r"(a2), "r"(a3), "r"(b0), "r"(b1));
}
#define CP_A16(dst, src) asm volatile("cp.async.ca.shared.global [%0], [%1], 16;" :: "r"(dst), "l"(src) : "memory")
#define CP_COMMIT()      asm volatile("cp.async.commit_group;" ::: "memory")
#define CP_WAIT0()       asm volatile("cp.async.wait_group 0;" ::: "memory")
#define STZ16(dst)       asm volatile("st.shared.v4.b32 [%0], {%1,%1,%1,%1};" :: "r"(dst), "r"(0u) : "memory")

// permuted position of channel c within its 16-group (f16 units):
// pair j=(c&15)>>1 -> base (j&3)*4 + (j>>2)*2; +(c&1)
__device__ __forceinline__ constexpr int pos16(int c15) {
    return (((c15 >> 1) & 3) << 2) + (((c15 >> 1) >> 2) << 1) + (c15 & 1);
}

// ================= fp16 m16n8k16 3x3 conv (NHWC-permuted fp16 in, pipelined cp.async) =================
// Block 256 threads (8 warps: 4 M x 2 N). 128 pixels x NTOT ch, 8 rows per block.
// A smem: [slot][ks-group][pixel][32B]; one LDS.64 per thread = fragment pair (k,k+1,k+8,k+9).
template<int CIN, int NSUB, bool H3>
__global__ __launch_bounds__(256) void mconv_k(
    const __half* __restrict__ in,
    const float* __restrict__ wA, const float* __restrict__ wB2, const float* __restrict__ wC,
    const float* __restrict__ bA, const float* __restrict__ bB2, const float* __restrict__ bC,
    const float* __restrict__ pr, void* __restrict__ outv)
{
    constexpr int NTOT = 2 * NSUB;
    constexpr int NKS = CIN / 16;            // 16-channel K-groups
    constexpr int SEGS = 2 * NKS;            // 16B segments per pixel
    constexpr int SLOTU2 = NKS * 130 * 4;    // uint2 units per slot

    extern __shared__ __align__(16) char smraw[];
    const uint2* a_u2 = (const uint2*)smraw;                 // 4 * SLOTU2
    uint2* w_u2 = (uint2*)smraw + 4 * SLOTU2;                // 9*NKS*NTOT*4
    const uint32_t a_u = smem_u32(smraw);

    const int tid = threadIdx.x;
    const int lane = tid & 31;
    const int wid = tid >> 5;
    const int g = lane >> 2, tg = lane & 3;
    const int mbase = (wid >> 1) * 32;
    const int nbase = (wid & 1) * NSUB;
    const int x0 = blockIdx.x * 128;
    const int y0 = blockIdx.y * 8;
    const int b = blockIdx.z;

    // ---- stage weights as fragment-ready 8B entries [tap][ks][n][tg] ----
    for (int i = tid; i < 9 * NKS * NTOT * 4; i += 256) {
        const int tap = i / (NKS * NTOT * 4);
        int r = i % (NKS * NTOT * 4);
        const int ks = r / (NTOT * 4);
        r %= NTOT * 4;
        const int n = r >> 2, t4 = r & 3;
        float v0 = 0.f, v1 = 0.f, v2 = 0.f, v3 = 0.f;
        const int cb = ks * 16 + t4 * 2;
        if (H3) {
            if (n < 12) {
                const float* wp = (n < 4) ? wA : (n < 8 ? wB2 : wC);
                const size_t nb = (size_t)(n & 3) * CIN;
                v0 = wp[(nb + cb) * 9 + tap];
                v1 = wp[(nb + cb + 1) * 9 + tap];
                v2 = wp[(nb + cb + 8) * 9 + tap];
                v3 = wp[(nb + cb + 9) * 9 + tap];
            }
        } else {
            const size_t nb = (size_t)n * CIN;
            v0 = wA[(nb + cb) * 9 + tap];
            v1 = wA[(nb + cb + 1) * 9 + tap];
            v2 = wA[(nb + cb + 8) * 9 + tap];
            v3 = wA[(nb + cb + 9) * 9 + tap];
        }
        uint2 e;
        e.x = pack_h2(v0, v1);
        e.y = pack_h2(v2, v3);
        w_u2[((tap * NKS + ks) * NTOT + n) * 4 + t4] = e;
    }

    const __half* inb = in + (size_t)b * HW * CIN;

    auto stage = [&](int yy) {
        const int slot = (yy + 4) & 3;
        const uint32_t sbase = a_u + (uint32_t)(slot * SLOTU2 * 8);
        const bool rok = ((unsigned)yy < HH);
        const __half* rowp = inb + (size_t)yy * WW * CIN;
        for (int i = tid; i < 130 * SEGS; i += 256) {
            const int p = i / SEGS;
            const int s = i % SEGS;
            const int ks = s >> 1, h = s & 1;
            const int gx = x0 + p - 1;
            const uint32_t dst = sbase + (uint32_t)(((ks * 130 + p) * 32) + h * 16);
            if (rok && (unsigned)gx < WW)
                CP_A16(dst, rowp + (size_t)gx * CIN + ks * 16 + h * 8);
            else
                STZ16(dst);
        }
    };

    stage(y0 - 1); stage(y0); stage(y0 + 1);
    CP_COMMIT();

    float* obF = (float*)outv + (size_t)b * HW * 16;          // H3 path
    __half* obH = (__half*)outv + (size_t)b * HW * NTOT;      // fp16 path
    const float alpha = pr ? pr[0] : 0.f;

    #pragma unroll 1
    for (int yi = 0; yi < 8; yi++) {
        const int y = y0 + yi;
        CP_WAIT0();
        __syncthreads();
        if (yi < 7) { stage(y + 2); CP_COMMIT(); }

        float acc[2][NSUB / 8][4];
        #pragma unroll
        for (int mt = 0; mt < 2; mt++)
            #pragma unroll
            for (int nt = 0; nt < NSUB / 8; nt++)
                #pragma unroll
                for (int e = 0; e < 4; e++) acc[mt][nt][e] = 0.f;

        #pragma unroll 1
        for (int tap = 0; tap < 9; tap++) {
            const int dy = tap / 3, dx = tap - dy * 3;
            const int slot = (y + dy + 3) & 3;
            #pragma unroll
            for (int ks = 0; ks < NKS; ks++) {
                const int base = (slot * NKS + ks) * 130 * 4;
                uint2 q0[2], q1[2];
                #pragma unroll
                for (int mt = 0; mt < 2; mt++) {
                    const int pix = mbase + mt * 16 + g + dx;
                    q0[mt] = a_u2[base + pix * 4 + tg];
                    q1[mt] = a_u2[base + (pix + 8) * 4 + tg];
                }
                #pragma unroll
                for (int nt = 0; nt < NSUB / 8; nt++) {
                    const uint2 qw = w_u2[((tap * NKS + ks) * NTOT + nbase + nt * 8 + g) * 4 + tg];
                    #pragma unroll
                    for (int mt = 0; mt < 2; mt++)
                        mma16(acc[mt][nt], q0[mt].x, q1[mt].x, q0[mt].y, q1[mt].y, qw.x, qw.y);
                }
            }
        }

        // ---- epilogue ----
        #pragma unroll
        for (int mt = 0; mt < 2; mt++) {
            const int px = x0 + mbase + mt * 16 + g;
            #pragma unroll
            for (int nt = 0; nt < NSUB / 8; nt++) {
                const int ch = nbase + nt * 8 + tg * 2;
                float v0 = acc[mt][nt][0] + (H3 ? (ch < 12 ? (ch < 4 ? bA : (ch < 8 ? bB2 : bC))[ch & 3] : 0.f) : bA[ch]);
                float v1 = acc[mt][nt][1] + (H3 ? (ch + 1 < 12 ? (ch + 1 < 4 ? bA : (ch + 1 < 8 ? bB2 : bC))[(ch + 1) & 3] : 0.f) : bA[ch + 1]);
                float v2 = acc[mt][nt][2] + (H3 ? (ch < 12 ? (ch < 4 ? bA : (ch < 8 ? bB2 : bC))[ch & 3] : 0.f) : bA[ch]);
                float v3 = acc[mt][nt][3] + (H3 ? (ch + 1 < 12 ? (ch + 1 < 4 ? bA : (ch + 1 < 8 ? bB2 : bC))[(ch + 1) & 3] : 0.f) : bA[ch + 1]);
                if (pr) {
                    if (v0 < 0.f) v0 *= alpha;
                    if (v1 < 0.f) v1 *= alpha;
                    if (v2 < 0.f) v2 *= alpha;
                    if (v3 < 0.f) v3 *= alpha;
                }
                if (H3) {
                    if (ch < 12) {
                        obF[((size_t)y * WW + px) * 16 + ch] = v0;
                        obF[((size_t)y * WW + px + 8) * 16 + ch] = v2;
                    }
                    if (ch + 1 < 12) {
                        obF[((size_t)y * WW + px) * 16 + ch + 1] = v1;
                        obF[((size_t)y * WW + px + 8) * 16 + ch + 1] = v3;
                    }
                } else {
                    const int grp = ch >> 4;
                    const int pos = pos16(ch & 15);
                    uint32_t lo = pack_h2(v0, v1), hi = pack_h2(v2, v3);
                    *(uint32_t*)(obH + ((size_t)y * WW + px) * NTOT + grp * 16 + pos) = lo;
                    *(uint32_t*)(obH + ((size_t)y * WW + px + 8) * NTOT + grp * 16 + pos) = hi;
                }
            }
        }
    }
}

// ================= conv1: 3->32 scalar, writes fp16 NHWC-permuted =================
__global__ __launch_bounds__(256) void conv1_k(
    const float* __restrict__ x, const float* __restrict__ w,
    const float* __restrict__ bias, const float* __restrict__ pr,
    __half* __restrict__ out)
{
    __shared__ float s_in[3][10][34];
    __shared__ float4 s_w4[27][8];
    __shared__ float s_b[32];

    const int tid = threadIdx.x;
    const int tx = tid & 31, ty = tid >> 5;
    const int x0 = blockIdx.x * 32, y0 = blockIdx.y * 8;
    const int b = blockIdx.z;

    for (int i = tid; i < 864; i += 256) {
        const int o = i / 27, t = i % 27;
        ((float*)s_w4)[t * 32 + o] = w[o * 27 + t];
    }
    if (tid < 32) s_b[tid] = bias[tid];
    for (int i = tid; i < 1020; i += 256) {
        const int c = i / 340, r = i % 340;
        const int rr = r / 34, cc = r % 34;
        const int gy = y0 - 1 + rr, gx = x0 - 1 + cc;
        float v = 0.f;
        if ((unsigned)gy < HH && (unsigned)gx < WW)
            v = x[((size_t)(b * 3 + c)) * HW + (size_t)gy * WW + gx];
        s_in[c][rr][cc] = v;
    }
    __syncthreads();

    float vin[27];
    #pragma unroll
    for (int c = 0; c < 3; c++)
        #pragma unroll
        for (int dy = 0; dy < 3; dy++)
            #pragma unroll
            for (int dx = 0; dx < 3; dx++)
                vin[c * 9 + dy * 3 + dx] = s_in[c][ty + dy][tx + dx];

    float acc[32];
    #pragma unroll
    for (int o = 0; o < 32; o++) acc[o] = 0.f;
    #pragma unroll
    for (int t = 0; t < 27; t++) {
        const float v = vin[t];
        #pragma unroll
        for (int og = 0; og < 8; og++) {
            const float4 wv = s_w4[t][og];
            acc[og * 4 + 0] += v * wv.x;
            acc[og * 4 + 1] += v * wv.y;
            acc[og * 4 + 2] += v * wv.z;
            acc[og * 4 + 3] += v * wv.w;
        }
    }

    const float alpha = pr[0];
    uint32_t uu[16];
    #pragma unroll
    for (int j = 0; j < 16; j++) {
        const int ch = 2 * j;
        float v0 = acc[ch] + s_b[ch];
        float v1 = acc[ch + 1] + s_b[ch + 1];
        if (v0 < 0.f) v0 *= alpha;
        if (v1 < 0.f) v1 *= alpha;
        const int jg = j & 7;
        const int slot = (j >> 3) * 8 + (jg & 3) * 2 + (jg >> 2);
        uu[slot] = pack_h2(v0, v1);
    }
    __half* dst = out + ((size_t)b * HW + (size_t)(y0 + ty) * WW + x0 + tx) * 32;
    #pragma unroll
    for (int q = 0; q < 4; q++)
        ((uint4*)dst)[q] = make_uint4(uu[4 * q], uu[4 * q + 1], uu[4 * q + 2], uu[4 * q + 3]);
}

// ================= GAP over fp32 NHWC16 head maps =================
__global__ __launch_bounds__(256) void gapp_k(const float* __restrict__ hp, float* __restrict__ part)
{
    __shared__ float red[8][12];
    const int b = blockIdx.x, seg = blockIdx.y;
    const int tid = threadIdx.x;
    const float* base = hp + ((size_t)b * HW + (size_t)seg * (HW / 16)) * 16;
    float s[12];
    #pragma unroll
    for (int c = 0; c < 12; c++) s[c] = 0.f;
    for (int i = tid; i < HW / 16; i += 256) {
        const float4* q = (const float4*)(base + (size_t)i * 16);
        const float4 A = q[0], B4 = q[1], C = q[2];
        s[0] += A.x;  s[1] += A.y;  s[2] += A.z;  s[3] += A.w;
        s[4] += B4.x; s[5] += B4.y; s[6] += B4.z; s[7] += B4.w;
        s[8] += C.x;  s[9] += C.y;  s[10] += C.z; s[11] += C.w;
    }
    #pragma unroll
    for (int k = 16; k > 0; k >>= 1)
        #pragma unroll
        for (int c = 0; c < 12; c++) s[c] += __shfl_xor_sync(0xffffffffu, s[c], k);
    if ((tid & 31) == 0)
        #pragma unroll
        for (int c = 0; c < 12; c++) red[tid >> 5][c] = s[c];
    __syncthreads();
    if (tid < 12) {
        float t = 0.f;
        #pragma unroll
        for (int wdx = 0; wdx < 8; wdx++) t += red[wdx][tid];
        part[((size_t)b * 16 + seg) * 12 + tid] = t;
    }
}

__global__ void gapc_k(const float* __restrict__ part, float* __restrict__ g)
{
    const int t = threadIdx.x;
    if (t < 96) {
        const int b = t / 12, c = t % 12;
        float s = 0.f;
        #pragma unroll
        for (int k = 0; k < 16; k++) s += part[((size_t)b * 16 + k) * 12 + c];
        g[(c >> 2) * 32 + b * 4 + (c & 3)] = s * (1.0f / HW);
    }
}

__global__ void se_k(const float* __restrict__ g, const float* __restrict__ c1,
                     const float* __restrict__ c2, float* __restrict__ s)
{
    __shared__ float t[BB][4];
    int tid = threadIdx.x;
    if (tid < BB * 4) {
        int b = tid >> 2, c = tid & 3;
        float v = 0.f;
        #pragma unroll
        for (int k = 0; k < 4; k++) v += c1[c * 4 + k] * g[b * 4 + k];
        t[b][c] = fmaxf(v, 0.f);
    }
    __syncthreads();
    if (tid < BB * 4) {
        int b = tid >> 2, c = tid & 3;
        float v = 0.f;
        #pragma unroll
        for (int k = 0; k < 4; k++) v += c2[c * 4 + k] * t[b][k];
        s[b * 4 + c] = 1.f / (1.f + __expf(-v));
    }
}

// ================= fused blur + softmax + combine (hp fp32 NHWC16) =================
__global__ __launch_bounds__(256) void blurfuse_k(
    const float* __restrict__ src, const float* __restrict__ hp, int hoff,
    const float* __restrict__ sv, float* __restrict__ out)
{
    __shared__ float s_src[56][57];
    __shared__ float s_h5[56][52];
    __shared__ float s_h15[56][32];
    __shared__ float s_h25[56][32];

    const int tid = threadIdx.y * 32 + threadIdx.x;
    const int tx = threadIdx.x, ty = threadIdx.y;
    const int x0 = blockIdx.x * 32, y0 = blockIdx.y * 32;
    const int z = blockIdx.z;
    const int c = z % 3, b = z / 3;
    const size_t cb = (size_t)(b * 3 + c) * HW;

    for (int i = tid; i < 56 * 56; i += 256) {
        const int r = i / 56, cc = i % 56;
        const int gy = y0 - 12 + r, gx = x0 - 12 + cc;
        float v = 0.f;
        if ((unsigned)gy < HH && (unsigned)gx < WW)
            v = src[cb + (size_t)gy * WW + gx];
        s_src[r][cc] = v;
    }
    __syncthreads();

    for (int i = tid; i < 56 * 52; i += 256) {
        const int r = i / 52, j = i % 52;
        s_h5[r][j] = s_src[r][j] + s_src[r][j + 1] + s_src[r][j + 2]
                   + s_src[r][j + 3] + s_src[r][j + 4];
    }
    __syncthreads();

    for (int i = tid; i < 56 * 32; i += 256) {
        const int r = i / 32, t = i % 32;
        const float h15 = s_h5[r][t + 5] + s_h5[r][t + 10] + s_h5[r][t + 15];
        s_h15[r][t] = h15;
        s_h25[r][t] = h15 + s_h5[r][t] + s_h5[r][t + 20];
    }
    __syncthreads();

    const int r0 = ty * 4 + 12;
    float v5 = 0.f, v15 = 0.f, v25 = 0.f;
    #pragma unroll
    for (int d = -2; d <= 2; d++) v5 += s_h5[r0 + d][tx + 10];
    #pragma unroll
    for (int d = -7; d <= 7; d++) v15 += s_h15[r0 + d][tx];
    #pragma unroll
    for (int d = -12; d <= 12; d++) v25 += s_h25[r0 + d][tx];

    const float s0 = sv[b * 4 + 0], s1 = sv[b * 4 + 1], s2 = sv[b * 4 + 2], s3 = sv[b * 4 + 3];
    const int x = x0 + tx;

    #pragma unroll
    for (int j = 0; j < 4; j++) {
        const int y = y0 + ty * 4 + j;
        const int r = r0 + j;
        const float4 hv = *(const float4*)(hp + ((size_t)b * HW + (size_t)y * WW + x) * 16 + hoff);
        float e0 = hv.x * s0, e1 = hv.y * s1, e2 = hv.z * s2, e3 = hv.w * s3;
        float m = fmaxf(fmaxf(e0, e1), fmaxf(e2, e3));
        float w0 = __expf(e0 - m), w1 = __expf(e1 - m), w2 = __expf(e2 - m), w3 = __expf(e3 - m);
        float inv = 1.f / (w0 + w1 + w2 + w3);
        float o = (w0 * inv) * s_src[r][tx + 12]
                + (w1 * inv) * (v5 * (1.f / 25.f))
                + (w2 * inv) * (v15 * (1.f / 225.f))
                + (w3 * inv) * (v25 * (1.f / 625.f));
        out[cb + (size_t)y * WW + x] = o;
        if (j < 3) {
            v5 += s_h5[r + 3][tx + 10] - s_h5[r - 2][tx + 10];
            v15 += s_h15[r + 8][tx] - s_h15[r - 7][tx];
            v25 += s_h25[r + 13][tx] - s_h25[r - 12][tx];
        }
    }
}

// ================= launch =================
extern "C" void kernel_launch(void* const* d_in, const int* in_sizes, int n_in,
                              void* d_out, int out_size)
{
    const float* x   = (const float*)d_in[0];
    const float* bw1 = (const float*)d_in[1];
    const float* bb1 = (const float*)d_in[2];
    const float* a1  = (const float*)d_in[3];
    const float* bw2 = (const float*)d_in[4];
    const float* bb2 = (const float*)d_in[5];
    const float* a2  = (const float*)d_in[6];
    const float* bw3 = (const float*)d_in[7];
    const float* bb3 = (const float*)d_in[8];
    const float* a3  = (const float*)d_in[9];
    const float* hw_[3]  = { (const float*)d_in[10], (const float*)d_in[14], (const float*)d_in[18] };
    const float* hb_[3]  = { (const float*)d_in[11], (const float*)d_in[15], (const float*)d_in[19] };
    const float* hc1_[3] = { (const float*)d_in[12], (const float*)d_in[16], (const float*)d_in[20] };
    const float* hc2_[3] = { (const float*)d_in[13], (const float*)d_in[17], (const float*)d_in[21] };

    float *B1, *B2, *G, *P, *S, *TX, *TX2;
    cudaGetSymbolAddress((void**)&B1, g_B1);
    cudaGetSymbolAddress((void**)&B2, g_B2);
    cudaGetSymbolAddress((void**)&G, g_G);
    cudaGetSymbolAddress((void**)&P, g_P);
    cudaGetSymbolAddress((void**)&S, g_S);
    cudaGetSymbolAddress((void**)&TX, g_TX);
    cudaGetSymbolAddress((void**)&TX2, g_TX2);
    __half* B1h = (__half*)B1;
    __half* B2h = (__half*)B2;

    // smem bytes: A = 4*NKS*130*32, W = 9*NKS*NTOT*32
    const int smem2 = 4 * 2 * 130 * 32 + 9 * 2 * 64 * 32;  // 70144
    const int smem3 = 4 * 4 * 130 * 32 + 9 * 4 * 32 * 32;  // 103424
    const int smemH = 4 * 2 * 130 * 32 + 9 * 2 * 16 * 32;  // 42496
    cudaFuncSetAttribute((const void*)mconv_k<32, 32, false>,
                         cudaFuncAttributeMaxDynamicSharedMemorySize, smem2);
    cudaFuncSetAttribute((const void*)mconv_k<64, 16, false>,
                         cudaFuncAttributeMaxDynamicSharedMemorySize, smem3);
    cudaFuncSetAttribute((const void*)mconv_k<32, 8, true>,
                         cudaFuncAttributeMaxDynamicSharedMemorySize, smemH);

    const dim3 tgrid(WW / 128, HH / 8, BB);

    // body
    conv1_k<<<dim3(16, 64, BB), 256>>>(x, bw1, bb1, a1, B1h);
    mconv_k<32, 32, false><<<tgrid, 256, smem2>>>(
        B1h, bw2, nullptr, nullptr, bb2, nullptr, nullptr, a2, B2h);
    mconv_k<64, 16, false><<<tgrid, 256, smem3>>>(
        B2h, bw3, nullptr, nullptr, bb3, nullptr, nullptr, a3, B1h);

    // heads fused -> fp32 NHWC16 HPA (reuse B2)
    float* HPA = B2;
    mconv_k<32, 8, true><<<tgrid, 256, smemH>>>(
        B1h, hw_[0], hw_[1], hw_[2], hb_[0], hb_[1], hb_[2], nullptr, HPA);
    gapp_k<<<dim3(BB, 16), 256>>>(HPA, P);
    gapc_k<<<1, 128>>>(P, G);
    for (int i = 0; i < 3; i++)
        se_k<<<1, 32>>>(G + i * 32, hc1_[i], hc2_[i], S + i * 32);

    // fused blur+softmax+combine (ping-pong)
    const dim3 fgrid(16, 16, BB * 3);
    const dim3 fblk(32, 8);
    blurfuse_k<<<fgrid, fblk>>>(x,   HPA, 0, S + 0,  TX);
    blurfuse_k<<<fgrid, fblk>>>(TX,  HPA, 4, S + 32, TX2);
    blurfuse_k<<<fgrid, fblk>>>(TX2, HPA, 8, S + 64, (float*)d_out);
    (void)in_sizes; (void)n_in; (void)out_size;
}

// round 7
// speedup vs baseline: 6.5234x; 1.0726x over previous
#include <cuda_runtime.h>
#include <cuda_fp16.h>
#include <cstdint>
#include <cstddef>

#define HH 512
#define WW 512
#define BB 8
constexpr int HW = HH * WW;

// ---------------- scratch ----------------
__device__ float g_B1[(size_t)BB * HW * 32 / 2];   // fp16 NHWC-permuted 32ch
__device__ float g_B2[(size_t)BB * HW * 64];       // fp16 64ch / fp32 HPA[16]
__device__ float g_G[3 * BB * 4];
__device__ float g_P[BB * 16 * 12];
__device__ float g_S[3 * BB * 4];
__device__ float g_TX[(size_t)BB * 3 * HW];
__device__ float g_TX2[(size_t)BB * 3 * HW];

// ---------------- helpers ----------------
__device__ __forceinline__ uint32_t smem_u32(const void* p) {
    uint32_t r;
    asm("{ .reg .u64 t; cvta.to.shared.u64 t, %1; cvt.u32.u64 %0, t; }" : "=r"(r) : "l"(p));
    return r;
}
__device__ __forceinline__ uint32_t pack_h2(float a, float b) {
    __half2 h = __floats2half2_rn(a, b);
    return *(uint32_t*)&h;
}
__device__ __forceinline__ void mma16(float* d, uint32_t a0, uint32_t a1, uint32_t a2,
                                      uint32_t a3, uint32_t b0, uint32_t b1) {
    asm volatile(
        "mma.sync.aligned.m16n8k16.row.col.f32.f16.f16.f32 "
        "{%0,%1,%2,%3}, {%4,%5,%6,%7}, {%8,%9}, {%0,%1,%2,%3};"
        : "+f"(d[0]), "+f"(d[1]), "+f"(d[2]), "+f"(d[3])
        : "r"(a0), "r"(a1), "r"(a2), "r"(a3), "r"(b0), "r"(b1));
}
#define CP_A16(dst, src) asm volatile("cp.async.ca.shared.global [%0], [%1], 16;" :: "r"(dst), "l"(src) : "memory")
#define CP_COMMIT()      asm volatile("cp.async.commit_group;" ::: "memory")
#define CP_WAIT0()       asm volatile("cp.async.wait_group 0;" ::: "memory")
#define STZ16(dst)       asm volatile("st.shared.v4.b32 [%0], {%1,%1,%1,%1};" :: "r"(dst), "r"(0u) : "memory")

__device__ __forceinline__ constexpr int pos16(int c15) {
    return (((c15 >> 1) & 3) << 2) + (((c15 >> 1) >> 2) << 1) + (c15 & 1);
}

// ================= fp16 m16n8k16 3x3 conv, generalized register tiling =================
// Block 256 threads = MW m-warps x (8/MW) n-warps; per-warp tile (MT*16) x (NT*8).
// Pixel tile P = MW*MT*16 per row, 8 rows per block, 4-slot cp.async row pipeline.
template<int CIN, int NTOT, int MW, int MT, int NT, bool H3>
__global__ __launch_bounds__(256) void mconv_k(
    const __half* __restrict__ in,
    const float* __restrict__ wA, const float* __restrict__ wB2, const float* __restrict__ wC,
    const float* __restrict__ bA, const float* __restrict__ bB2, const float* __restrict__ bC,
    const float* __restrict__ pr, void* __restrict__ outv)
{
    constexpr int P = MW * MT * 16;
    constexpr int PP = P + 2;
    constexpr int NKS = CIN / 16;
    constexpr int SEGS = 2 * NKS;
    constexpr int SLOTU2 = NKS * PP * 4;

    extern __shared__ __align__(16) char smraw[];
    const uint2* a_u2 = (const uint2*)smraw;
    uint2* w_u2 = (uint2*)smraw + 4 * SLOTU2;
    const uint32_t a_u = smem_u32(smraw);

    const int tid = threadIdx.x;
    const int lane = tid & 31;
    const int wid = tid >> 5;
    const int g = lane >> 2, tg = lane & 3;
    const int mbase = (wid % MW) * MT * 16;
    const int nbase = (wid / MW) * NT * 8;
    const int x0 = blockIdx.x * P;
    const int y0 = blockIdx.y * 8;
    const int b = blockIdx.z;

    // ---- weights as fragment-ready 8B entries [tap][ks][n][tg] ----
    for (int i = tid; i < 9 * NKS * NTOT * 4; i += 256) {
        const int tap = i / (NKS * NTOT * 4);
        int r = i % (NKS * NTOT * 4);
        const int ks = r / (NTOT * 4);
        r %= NTOT * 4;
        const int n = r >> 2, t4 = r & 3;
        float v0 = 0.f, v1 = 0.f, v2 = 0.f, v3 = 0.f;
        const int cb = ks * 16 + t4 * 2;
        if (H3) {
            if (n < 12) {
                const float* wp = (n < 4) ? wA : (n < 8 ? wB2 : wC);
                const size_t nb = (size_t)(n & 3) * CIN;
                v0 = wp[(nb + cb) * 9 + tap];
                v1 = wp[(nb + cb + 1) * 9 + tap];
                v2 = wp[(nb + cb + 8) * 9 + tap];
                v3 = wp[(nb + cb + 9) * 9 + tap];
            }
        } else {
            const size_t nb = (size_t)n * CIN;
            v0 = wA[(nb + cb) * 9 + tap];
            v1 = wA[(nb + cb + 1) * 9 + tap];
            v2 = wA[(nb + cb + 8) * 9 + tap];
            v3 = wA[(nb + cb + 9) * 9 + tap];
        }
        uint2 e;
        e.x = pack_h2(v0, v1);
        e.y = pack_h2(v2, v3);
        w_u2[((tap * NKS + ks) * NTOT + n) * 4 + t4] = e;
    }

    const __half* inb = in + (size_t)b * HW * CIN;

    auto stage = [&](int yy) {
        const int slot = (yy + 4) & 3;
        const uint32_t sbase = a_u + (uint32_t)(slot * SLOTU2 * 8);
        const bool rok = ((unsigned)yy < HH);
        const __half* rowp = inb + (size_t)yy * WW * CIN;
        for (int i = tid; i < PP * SEGS; i += 256) {
            const int p = i / SEGS;
            const int s = i % SEGS;
            const int ks = s >> 1, h = s & 1;
            const int gx = x0 + p - 1;
            const uint32_t dst = sbase + (uint32_t)(((ks * PP + p) * 32) + h * 16);
            if (rok && (unsigned)gx < WW)
                CP_A16(dst, rowp + (size_t)gx * CIN + ks * 16 + h * 8);
            else
                STZ16(dst);
        }
    };

    stage(y0 - 1); stage(y0); stage(y0 + 1);
    CP_COMMIT();

    float* obF = (float*)outv + (size_t)b * HW * 16;
    __half* obH = (__half*)outv + (size_t)b * HW * NTOT;
    const float alpha = pr ? pr[0] : 0.f;

    #pragma unroll 1
    for (int yi = 0; yi < 8; yi++) {
        const int y = y0 + yi;
        CP_WAIT0();
        __syncthreads();
        if (yi < 7) { stage(y + 2); CP_COMMIT(); }

        float acc[MT][NT][4];
        #pragma unroll
        for (int mt = 0; mt < MT; mt++)
            #pragma unroll
            for (int nt = 0; nt < NT; nt++)
                #pragma unroll
                for (int e = 0; e < 4; e++) acc[mt][nt][e] = 0.f;

        #pragma unroll 1
        for (int tap = 0; tap < 9; tap++) {
            const int dy = tap / 3, dx = tap - dy * 3;
            const int slot = (y + dy + 3) & 3;
            #pragma unroll
            for (int ks = 0; ks < NKS; ks++) {
                const int base = (slot * NKS + ks) * PP * 4;
                uint2 q0[MT], q1[MT];
                #pragma unroll
                for (int mt = 0; mt < MT; mt++) {
                    const int pix = mbase + mt * 16 + g + dx;
                    q0[mt] = a_u2[base + pix * 4 + tg];
                    q1[mt] = a_u2[base + (pix + 8) * 4 + tg];
                }
                #pragma unroll
                for (int nt = 0; nt < NT; nt++) {
                    const uint2 qw = w_u2[((tap * NKS + ks) * NTOT + nbase + nt * 8 + g) * 4 + tg];
                    #pragma unroll
                    for (int mt = 0; mt < MT; mt++)
                        mma16(acc[mt][nt], q0[mt].x, q1[mt].x, q0[mt].y, q1[mt].y, qw.x, qw.y);
                }
            }
        }

        // ---- epilogue ----
        #pragma unroll
        for (int mt = 0; mt < MT; mt++) {
            const int px = x0 + mbase + mt * 16 + g;
            #pragma unroll
            for (int nt = 0; nt < NT; nt++) {
                const int ch = nbase + nt * 8 + tg * 2;
                float bv0, bv1;
                if (H3) {
                    bv0 = (ch < 12) ? (ch < 4 ? bA : (ch < 8 ? bB2 : bC))[ch & 3] : 0.f;
                    bv1 = (ch + 1 < 12) ? (ch + 1 < 4 ? bA : (ch + 1 < 8 ? bB2 : bC))[(ch + 1) & 3] : 0.f;
                } else {
                    bv0 = bA[ch]; bv1 = bA[ch + 1];
                }
                float v0 = acc[mt][nt][0] + bv0;
                float v1 = acc[mt][nt][1] + bv1;
                float v2 = acc[mt][nt][2] + bv0;
                float v3 = acc[mt][nt][3] + bv1;
                if (pr) {
                    if (v0 < 0.f) v0 *= alpha;
                    if (v1 < 0.f) v1 *= alpha;
                    if (v2 < 0.f) v2 *= alpha;
                    if (v3 < 0.f) v3 *= alpha;
                }
                if (H3) {
                    if (ch < 12) {
                        obF[((size_t)y * WW + px) * 16 + ch] = v0;
                        obF[((size_t)y * WW + px + 8) * 16 + ch] = v2;
                    }
                    if (ch + 1 < 12) {
                        obF[((size_t)y * WW + px) * 16 + ch + 1] = v1;
                        obF[((size_t)y * WW + px + 8) * 16 + ch + 1] = v3;
                    }
                } else {
                    const int grp = ch >> 4;
                    const int pos = pos16(ch & 15);
                    *(uint32_t*)(obH + ((size_t)y * WW + px) * NTOT + grp * 16 + pos) = pack_h2(v0, v1);
                    *(uint32_t*)(obH + ((size_t)y * WW + px + 8) * NTOT + grp * 16 + pos) = pack_h2(v2, v3);
                }
            }
        }
    }
}

// ================= conv1: 3->32 scalar, fp16 NHWC-permuted out =================
__global__ __launch_bounds__(256) void conv1_k(
    const float* __restrict__ x, const float* __restrict__ w,
    const float* __restrict__ bias, const float* __restrict__ pr,
    __half* __restrict__ out)
{
    __shared__ float s_in[3][10][34];
    __shared__ float4 s_w4[27][8];
    __shared__ float s_b[32];

    const int tid = threadIdx.x;
    const int tx = tid & 31, ty = tid >> 5;
    const int x0 = blockIdx.x * 32, y0 = blockIdx.y * 8;
    const int b = blockIdx.z;

    for (int i = tid; i < 864; i += 256) {
        const int o = i / 27, t = i % 27;
        ((float*)s_w4)[t * 32 + o] = w[o * 27 + t];
    }
    if (tid < 32) s_b[tid] = bias[tid];
    for (int i = tid; i < 1020; i += 256) {
        const int c = i / 340, r = i % 340;
        const int rr = r / 34, cc = r % 34;
        const int gy = y0 - 1 + rr, gx = x0 - 1 + cc;
        float v = 0.f;
        if ((unsigned)gy < HH && (unsigned)gx < WW)
            v = x[((size_t)(b * 3 + c)) * HW + (size_t)gy * WW + gx];
        s_in[c][rr][cc] = v;
    }
    __syncthreads();

    float vin[27];
    #pragma unroll
    for (int c = 0; c < 3; c++)
        #pragma unroll
        for (int dy = 0; dy < 3; dy++)
            #pragma unroll
            for (int dx = 0; dx < 3; dx++)
                vin[c * 9 + dy * 3 + dx] = s_in[c][ty + dy][tx + dx];

    float acc[32];
    #pragma unroll
    for (int o = 0; o < 32; o++) acc[o] = 0.f;
    #pragma unroll
    for (int t = 0; t < 27; t++) {
        const float v = vin[t];
        #pragma unroll
        for (int og = 0; og < 8; og++) {
            const float4 wv = s_w4[t][og];
            acc[og * 4 + 0] += v * wv.x;
            acc[og * 4 + 1] += v * wv.y;
            acc[og * 4 + 2] += v * wv.z;
            acc[og * 4 + 3] += v * wv.w;
        }
    }

    const float alpha = pr[0];
    uint32_t uu[16];
    #pragma unroll
    for (int j = 0; j < 16; j++) {
        const int ch = 2 * j;
        float v0 = acc[ch] + s_b[ch];
        float v1 = acc[ch + 1] + s_b[ch + 1];
        if (v0 < 0.f) v0 *= alpha;
        if (v1 < 0.f) v1 *= alpha;
        const int jg = j & 7;
        const int slot = (j >> 3) * 8 + (jg & 3) * 2 + (jg >> 2);
        uu[slot] = pack_h2(v0, v1);
    }
    __half* dst = out + ((size_t)b * HW + (size_t)(y0 + ty) * WW + x0 + tx) * 32;
    #pragma unroll
    for (int q = 0; q < 4; q++)
        ((uint4*)dst)[q] = make_uint4(uu[4 * q], uu[4 * q + 1], uu[4 * q + 2], uu[4 * q + 3]);
}

// ================= GAP / SE =================
__global__ __launch_bounds__(256) void gapp_k(const float* __restrict__ hp, float* __restrict__ part)
{
    __shared__ float red[8][12];
    const int b = blockIdx.x, seg = blockIdx.y;
    const int tid = threadIdx.x;
    const float* base = hp + ((size_t)b * HW + (size_t)seg * (HW / 16)) * 16;
    float s[12];
    #pragma unroll
    for (int c = 0; c < 12; c++) s[c] = 0.f;
    for (int i = tid; i < HW / 16; i += 256) {
        const float4* q = (const float4*)(base + (size_t)i * 16);
        const float4 A = q[0], B4 = q[1], C = q[2];
        s[0] += A.x;  s[1] += A.y;  s[2] += A.z;  s[3] += A.w;
        s[4] += B4.x; s[5] += B4.y; s[6] += B4.z; s[7] += B4.w;
        s[8] += C.x;  s[9] += C.y;  s[10] += C.z; s[11] += C.w;
    }
    #pragma unroll
    for (int k = 16; k > 0; k >>= 1)
        #pragma unroll
        for (int c = 0; c < 12; c++) s[c] += __shfl_xor_sync(0xffffffffu, s[c], k);
    if ((tid & 31) == 0)
        #pragma unroll
        for (int c = 0; c < 12; c++) red[tid >> 5][c] = s[c];
    __syncthreads();
    if (tid < 12) {
        float t = 0.f;
        #pragma unroll
        for (int wdx = 0; wdx < 8; wdx++) t += red[wdx][tid];
        part[((size_t)b * 16 + seg) * 12 + tid] = t;
    }
}

__global__ void gapc_k(const float* __restrict__ part, float* __restrict__ g)
{
    const int t = threadIdx.x;
    if (t < 96) {
        const int b = t / 12, c = t % 12;
        float s = 0.f;
        #pragma unroll
        for (int k = 0; k < 16; k++) s += part[((size_t)b * 16 + k) * 12 + c];
        g[(c >> 2) * 32 + b * 4 + (c & 3)] = s * (1.0f / HW);
    }
}

__global__ void se_k(const float* __restrict__ g, const float* __restrict__ c1,
                     const float* __restrict__ c2, float* __restrict__ s)
{
    __shared__ float t[BB][4];
    int tid = threadIdx.x;
    if (tid < BB * 4) {
        int b = tid >> 2, c = tid & 3;
        float v = 0.f;
        #pragma unroll
        for (int k = 0; k < 4; k++) v += c1[c * 4 + k] * g[b * 4 + k];
        t[b][c] = fmaxf(v, 0.f);
    }
    __syncthreads();
    if (tid < BB * 4) {
        int b = tid >> 2, c = tid & 3;
        float v = 0.f;
        #pragma unroll
        for (int k = 0; k < 4; k++) v += c2[c * 4 + k] * t[b][k];
        s[b * 4 + c] = 1.f / (1.f + __expf(-v));
    }
}

// ================= fused blur + softmax + combine, 64x64 tiles =================
__global__ __launch_bounds__(256) void blurfuse_k(
    const float* __restrict__ src, const float* __restrict__ hp, int hoff,
    const float* __restrict__ sv, float* __restrict__ out)
{
    extern __shared__ float bsm[];
    float (*s_src)[89] = (float(*)[89])bsm;                       // 88 x 89
    float (*s_h5)[84]  = (float(*)[84])(bsm + 88 * 89);           // 88 x 84
    float (*s_h15)[64] = (float(*)[64])(bsm + 88 * 89 + 88 * 84); // 88 x 64
    float (*s_h25)[64] = (float(*)[64])(bsm + 88 * 89 + 88 * 84 + 88 * 64);

    const int tx = threadIdx.x, ty = threadIdx.y;   // 64 x 4
    const int tid = ty * 64 + tx;
    const int x0 = blockIdx.x * 64, y0 = blockIdx.y * 64;
    const int z = blockIdx.z;
    const int c = z % 3, b = z / 3;
    const size_t cb = (size_t)(b * 3 + c) * HW;

    for (int i = tid; i < 88 * 88; i += 256) {
        const int r = i / 88, cc = i % 88;
        const int gy = y0 - 12 + r, gx = x0 - 12 + cc;
        float v = 0.f;
        if ((unsigned)gy < HH && (unsigned)gx < WW)
            v = src[cb + (size_t)gy * WW + gx];
        s_src[r][cc] = v;
    }
    __syncthreads();

    for (int i = tid; i < 88 * 84; i += 256) {
        const int r = i / 84, j = i % 84;
        s_h5[r][j] = s_src[r][j] + s_src[r][j + 1] + s_src[r][j + 2]
                   + s_src[r][j + 3] + s_src[r][j + 4];
    }
    __syncthreads();

    for (int i = tid; i < 88 * 64; i += 256) {
        const int r = i / 64, t = i % 64;
        const float h15 = s_h5[r][t + 5] + s_h5[r][t + 10] + s_h5[r][t + 15];
        s_h15[r][t] = h15;
        s_h25[r][t] = h15 + s_h5[r][t] + s_h5[r][t + 20];
    }
    __syncthreads();

    const int r0 = ty * 16 + 12;
    float v5 = 0.f, v15 = 0.f, v25 = 0.f;
    #pragma unroll
    for (int d = -2; d <= 2; d++) v5 += s_h5[r0 + d][tx + 10];
    #pragma unroll
    for (int d = -7; d <= 7; d++) v15 += s_h15[r0 + d][tx];
    #pragma unroll
    for (int d = -12; d <= 12; d++) v25 += s_h25[r0 + d][tx];

    const float s0 = sv[b * 4 + 0], s1 = sv[b * 4 + 1], s2 = sv[b * 4 + 2], s3 = sv[b * 4 + 3];
    const int x = x0 + tx;

    #pragma unroll 1
    for (int j = 0; j < 16; j++) {
        const int y = y0 + ty * 16 + j;
        const int r = r0 + j;
        const float4 hv = *(const float4*)(hp + ((size_t)b * HW + (size_t)y * WW + x) * 16 + hoff);
        float e0 = hv.x * s0, e1 = hv.y * s1, e2 = hv.z * s2, e3 = hv.w * s3;
        float m = fmaxf(fmaxf(e0, e1), fmaxf(e2, e3));
        float w0 = __expf(e0 - m), w1 = __expf(e1 - m), w2 = __expf(e2 - m), w3 = __expf(e3 - m);
        float inv = 1.f / (w0 + w1 + w2 + w3);
        float o = (w0 * inv) * s_src[r][tx + 12]
                + (w1 * inv) * (v5 * (1.f / 25.f))
                + (w2 * inv) * (v15 * (1.f / 225.f))
                + (w3 * inv) * (v25 * (1.f / 625.f));
        out[cb + (size_t)y * WW + x] = o;
        if (j < 15) {
            v5 += s_h5[r + 3][tx + 10] - s_h5[r - 2][tx + 10];
            v15 += s_h15[r + 8][tx] - s_h15[r - 7][tx];
            v25 += s_h25[r + 13][tx] - s_h25[r - 12][tx];
        }
    }
}

// ================= launch =================
extern "C" void kernel_launch(void* const* d_in, const int* in_sizes, int n_in,
                              void* d_out, int out_size)
{
    const float* x   = (const float*)d_in[0];
    const float* bw1 = (const float*)d_in[1];
    const float* bb1 = (const float*)d_in[2];
    const float* a1  = (const float*)d_in[3];
    const float* bw2 = (const float*)d_in[4];
    const float* bb2 = (const float*)d_in[5];
    const float* a2  = (const float*)d_in[6];
    const float* bw3 = (const float*)d_in[7];
    const float* bb3 = (const float*)d_in[8];
    const float* a3  = (const float*)d_in[9];
    const float* hw_[3]  = { (const float*)d_in[10], (const float*)d_in[14], (const float*)d_in[18] };
    const float* hb_[3]  = { (const float*)d_in[11], (const float*)d_in[15], (const float*)d_in[19] };
    const float* hc1_[3] = { (const float*)d_in[12], (const float*)d_in[16], (const float*)d_in[20] };
    const float* hc2_[3] = { (const float*)d_in[13], (const float*)d_in[17], (const float*)d_in[21] };

    float *B1, *B2, *G, *P, *S, *TX, *TX2;
    cudaGetSymbolAddress((void**)&B1, g_B1);
    cudaGetSymbolAddress((void**)&B2, g_B2);
    cudaGetSymbolAddress((void**)&G, g_G);
    cudaGetSymbolAddress((void**)&P, g_P);
    cudaGetSymbolAddress((void**)&S, g_S);
    cudaGetSymbolAddress((void**)&TX, g_TX);
    cudaGetSymbolAddress((void**)&TX2, g_TX2);
    __half* B1h = (__half*)B1;
    __half* B2h = (__half*)B2;

    // smem: A = 4*NKS*258*32, W = 9*NKS*NTOT*32
    const int smem2 = 4 * 2 * 258 * 32 + 9 * 2 * 64 * 32;  // 102912
    const int smem3 = 4 * 4 * 258 * 32 + 9 * 4 * 32 * 32;  // 168960
    const int smemH = 4 * 2 * 258 * 32 + 9 * 2 * 16 * 32;  // 75264
    const int smemF = (88 * 89 + 88 * 84 + 2 * 88 * 64) * 4;  // 105952
    cudaFuncSetAttribute((const void*)mconv_k<32, 64, 4, 4, 4, false>,
                         cudaFuncAttributeMaxDynamicSharedMemorySize, smem2);
    cudaFuncSetAttribute((const void*)mconv_k<64, 32, 8, 2, 4, false>,
                         cudaFuncAttributeMaxDynamicSharedMemorySize, smem3);
    cudaFuncSetAttribute((const void*)mconv_k<32, 16, 8, 2, 2, true>,
                         cudaFuncAttributeMaxDynamicSharedMemorySize, smemH);
    cudaFuncSetAttribute((const void*)blurfuse_k,
                         cudaFuncAttributeMaxDynamicSharedMemorySize, smemF);

    const dim3 tgrid(WW / 256, HH / 8, BB);

    // body
    conv1_k<<<dim3(16, 64, BB), 256>>>(x, bw1, bb1, a1, B1h);
    mconv_k<32, 64, 4, 4, 4, false><<<tgrid, 256, smem2>>>(
        B1h, bw2, nullptr, nullptr, bb2, nullptr, nullptr, a2, B2h);
    mconv_k<64, 32, 8, 2, 4, false><<<tgrid, 256, smem3>>>(
        B2h, bw3, nullptr, nullptr, bb3, nullptr, nullptr, a3, B1h);

    // heads fused -> fp32 NHWC16 HPA (reuse B2)
    float* HPA = B2;
    mconv_k<32, 16, 8, 2, 2, true><<<tgrid, 256, smemH>>>(
        B1h, hw_[0], hw_[1], hw_[2], hb_[0], hb_[1], hb_[2], nullptr, HPA);
    gapp_k<<<dim3(BB, 16), 256>>>(HPA, P);
    gapc_k<<<1, 128>>>(P, G);
    for (int i = 0; i < 3; i++)
        se_k<<<1, 32>>>(G + i * 32, hc1_[i], hc2_[i], S + i * 32);

    // fused blur+softmax+combine (64x64 tiles, ping-pong)
    const dim3 fgrid(8, 8, BB * 3);
    const dim3 fblk(64, 4);
    blurfuse_k<<<fgrid, fblk, smemF>>>(x,   HPA, 0, S + 0,  TX);
    blurfuse_k<<<fgrid, fblk, smemF>>>(TX,  HPA, 4, S + 32, TX2);
    blurfuse_k<<<fgrid, fblk, smemF>>>(TX2, HPA, 8, S + 64, (float*)d_out);
    (void)in_sizes; (void)n_in; (void)out_size;
}

// round 8
// speedup vs baseline: 6.9834x; 1.0705x over previous
#include <cuda_runtime.h>
#include <cuda_fp16.h>
#include <cstdint>
#include <cstddef>

#define HH 512
#define WW 512
#define BB 8
constexpr int HW = HH * WW;

// ---------------- scratch ----------------
__device__ float g_B1[(size_t)BB * HW * 32 / 2];   // fp16 NHWC-permuted 32ch
__device__ float g_B2[(size_t)BB * HW * 64];       // fp16 64ch / fp32 HPA[16]
__device__ float g_G[3 * BB * 4];
__device__ float g_P[BB * 16 * 12];
__device__ float g_S[3 * BB * 4];
__device__ float g_TX[(size_t)BB * 3 * HW];
__device__ float g_TX2[(size_t)BB * 3 * HW];
__device__ uint2 g_W2[9 * 2 * 64 * 4];
__device__ uint2 g_W3[9 * 4 * 32 * 4];
__device__ uint2 g_WH[9 * 2 * 16 * 4];

// ---------------- helpers ----------------
__device__ __forceinline__ uint32_t smem_u32(const void* p) {
    uint32_t r;
    asm("{ .reg .u64 t; cvta.to.shared.u64 t, %1; cvt.u32.u64 %0, t; }" : "=r"(r) : "l"(p));
    return r;
}
__device__ __forceinline__ uint32_t pack_h2(float a, float b) {
    __half2 h = __floats2half2_rn(a, b);
    return *(uint32_t*)&h;
}
__device__ __forceinline__ void mma16(float* d, uint32_t a0, uint32_t a1, uint32_t a2,
                                      uint32_t a3, uint32_t b0, uint32_t b1) {
    asm volatile(
        "mma.sync.aligned.m16n8k16.row.col.f32.f16.f16.f32 "
        "{%0,%1,%2,%3}, {%4,%5,%6,%7}, {%8,%9}, {%0,%1,%2,%3};"
        : "+f"(d[0]), "+f"(d[1]), "+f"(d[2]), "+f"(d[3])
        : "r"(a0), "r"(a1), "r"(a2), "r"(a3), "r"(b0), "r"(b1));
}
__device__ __forceinline__ void fma2(unsigned long long& d, unsigned long long a,
                                     unsigned long long b) {
    asm("fma.rn.f32x2 %0, %1, %2, %0;" : "+l"(d) : "l"(a), "l"(b));
}
#define CP_A16(dst, src) asm volatile("cp.async.ca.shared.global [%0], [%1], 16;" :: "r"(dst), "l"(src) : "memory")
#define CP_COMMIT()      asm volatile("cp.async.commit_group;" ::: "memory")
#define CP_WAIT0()       asm volatile("cp.async.wait_group 0;" ::: "memory")
#define STZ16(dst)       asm volatile("st.shared.v4.b32 [%0], {%1,%1,%1,%1};" :: "r"(dst), "r"(0u) : "memory")

__device__ __forceinline__ constexpr int pos16(int c15) {
    return (((c15 >> 1) & 3) << 2) + (((c15 >> 1) >> 2) << 1) + (c15 & 1);
}

// ================= weight pre-transform (run once, tiny) =================
// Produces fragment-ready 8B entries [tap][ks][n][tg] identical to prior in-kernel layout.
__global__ void wprep_k(const float* __restrict__ wA, const float* __restrict__ wB2,
                        const float* __restrict__ wC, int CIN, int NTOT, int H3,
                        uint2* __restrict__ out, int total)
{
    const int i = blockIdx.x * 256 + threadIdx.x;
    if (i >= total) return;
    const int NKS = CIN / 16;
    const int tap = i / (NKS * NTOT * 4);
    int r = i % (NKS * NTOT * 4);
    const int ks = r / (NTOT * 4);
    r %= NTOT * 4;
    const int n = r >> 2, t4 = r & 3;
    float v0 = 0.f, v1 = 0.f, v2 = 0.f, v3 = 0.f;
    const int cb = ks * 16 + t4 * 2;
    if (H3) {
        if (n < 12) {
            const float* wp = (n < 4) ? wA : (n < 8 ? wB2 : wC);
            const size_t nb = (size_t)(n & 3) * CIN;
            v0 = wp[(nb + cb) * 9 + tap];
            v1 = wp[(nb + cb + 1) * 9 + tap];
            v2 = wp[(nb + cb + 8) * 9 + tap];
            v3 = wp[(nb + cb + 9) * 9 + tap];
        }
    } else {
        const size_t nb = (size_t)n * CIN;
        v0 = wA[(nb + cb) * 9 + tap];
        v1 = wA[(nb + cb + 1) * 9 + tap];
        v2 = wA[(nb + cb + 8) * 9 + tap];
        v3 = wA[(nb + cb + 9) * 9 + tap];
    }
    uint2 e;
    e.x = pack_h2(v0, v1);
    e.y = pack_h2(v2, v3);
    out[i] = e;
}

// ================= fp16 m16n8k16 3x3 conv, register tiling + cp.async weights =================
template<int CIN, int NTOT, int MW, int MT, int NT, bool H3>
__global__ __launch_bounds__(256) void mconv_k(
    const __half* __restrict__ in, const uint2* __restrict__ wp,
    const float* __restrict__ bA, const float* __restrict__ bB2, const float* __restrict__ bC,
    const float* __restrict__ pr, void* __restrict__ outv)
{
    constexpr int P = MW * MT * 16;
    constexpr int PP = P + 2;
    constexpr int NKS = CIN / 16;
    constexpr int SEGS = 2 * NKS;
    constexpr int SLOTU2 = NKS * PP * 4;
    constexpr int WSEGS = 9 * NKS * NTOT * 2;   // 16B segments of weights

    extern __shared__ __align__(16) char smraw[];
    const uint2* a_u2 = (const uint2*)smraw;
    const uint2* w_u2 = (const uint2*)smraw + 4 * SLOTU2;
    const uint32_t a_u = smem_u32(smraw);
    const uint32_t w_addr = a_u + (uint32_t)(4 * SLOTU2 * 8);

    const int tid = threadIdx.x;
    const int lane = tid & 31;
    const int wid = tid >> 5;
    const int g = lane >> 2, tg = lane & 3;
    const int mbase = (wid % MW) * MT * 16;
    const int nbase = (wid / MW) * NT * 8;
    const int x0 = blockIdx.x * P;
    const int y0 = blockIdx.y * 8;
    const int b = blockIdx.z;

    const __half* inb = in + (size_t)b * HW * CIN;

    auto stage = [&](int yy) {
        const int slot = (yy + 4) & 3;
        const uint32_t sbase = a_u + (uint32_t)(slot * SLOTU2 * 8);
        const bool rok = ((unsigned)yy < HH);
        const __half* rowp = inb + (size_t)yy * WW * CIN;
        for (int i = tid; i < PP * SEGS; i += 256) {
            const int p = i / SEGS;
            const int s = i % SEGS;
            const int ks = s >> 1, h = s & 1;
            const int gx = x0 + p - 1;
            const uint32_t dst = sbase + (uint32_t)(((ks * PP + p) * 32) + h * 16);
            if (rok && (unsigned)gx < WW)
                CP_A16(dst, rowp + (size_t)gx * CIN + ks * 16 + h * 8);
            else
                STZ16(dst);
        }
    };

    // weights + first rows in one async group
    for (int i = tid; i < WSEGS; i += 256)
        CP_A16(w_addr + (uint32_t)i * 16, (const char*)wp + (size_t)i * 16);
    stage(y0 - 1); stage(y0); stage(y0 + 1);
    CP_COMMIT();

    float* obF = (float*)outv + (size_t)b * HW * 16;
    __half* obH = (__half*)outv + (size_t)b * HW * NTOT;
    const float alpha = pr ? pr[0] : 0.f;

    #pragma unroll 1
    for (int yi = 0; yi < 8; yi++) {
        const int y = y0 + yi;
        CP_WAIT0();
        __syncthreads();
        if (yi < 7) { stage(y + 2); CP_COMMIT(); }

        float acc[MT][NT][4];
        #pragma unroll
        for (int mt = 0; mt < MT; mt++)
            #pragma unroll
            for (int nt = 0; nt < NT; nt++)
                #pragma unroll
                for (int e = 0; e < 4; e++) acc[mt][nt][e] = 0.f;

        #pragma unroll 1
        for (int tap = 0; tap < 9; tap++) {
            const int dy = tap / 3, dx = tap - dy * 3;
            const int slot = (y + dy + 3) & 3;
            #pragma unroll
            for (int ks = 0; ks < NKS; ks++) {
                const int base = (slot * NKS + ks) * PP * 4;
                uint2 q0[MT], q1[MT];
                #pragma unroll
                for (int mt = 0; mt < MT; mt++) {
                    const int pix = mbase + mt * 16 + g + dx;
                    q0[mt] = a_u2[base + pix * 4 + tg];
                    q1[mt] = a_u2[base + (pix + 8) * 4 + tg];
                }
                #pragma unroll
                for (int nt = 0; nt < NT; nt++) {
                    const uint2 qw = w_u2[((tap * NKS + ks) * NTOT + nbase + nt * 8 + g) * 4 + tg];
                    #pragma unroll
                    for (int mt = 0; mt < MT; mt++)
                        mma16(acc[mt][nt], q0[mt].x, q1[mt].x, q0[mt].y, q1[mt].y, qw.x, qw.y);
                }
            }
        }

        // ---- epilogue ----
        #pragma unroll
        for (int mt = 0; mt < MT; mt++) {
            const int px = x0 + mbase + mt * 16 + g;
            #pragma unroll
            for (int nt = 0; nt < NT; nt++) {
                const int ch = nbase + nt * 8 + tg * 2;
                float bv0, bv1;
                if (H3) {
                    bv0 = (ch < 12) ? (ch < 4 ? bA : (ch < 8 ? bB2 : bC))[ch & 3] : 0.f;
                    bv1 = (ch + 1 < 12) ? (ch + 1 < 4 ? bA : (ch + 1 < 8 ? bB2 : bC))[(ch + 1) & 3] : 0.f;
                } else {
                    bv0 = bA[ch]; bv1 = bA[ch + 1];
                }
                float v0 = acc[mt][nt][0] + bv0;
                float v1 = acc[mt][nt][1] + bv1;
                float v2 = acc[mt][nt][2] + bv0;
                float v3 = acc[mt][nt][3] + bv1;
                if (pr) {
                    if (v0 < 0.f) v0 *= alpha;
                    if (v1 < 0.f) v1 *= alpha;
                    if (v2 < 0.f) v2 *= alpha;
                    if (v3 < 0.f) v3 *= alpha;
                }
                if (H3) {
                    if (ch < 12) {
                        obF[((size_t)y * WW + px) * 16 + ch] = v0;
                        obF[((size_t)y * WW + px + 8) * 16 + ch] = v2;
                    }
                    if (ch + 1 < 12) {
                        obF[((size_t)y * WW + px) * 16 + ch + 1] = v1;
                        obF[((size_t)y * WW + px + 8) * 16 + ch + 1] = v3;
                    }
                } else {
                    const int grp = ch >> 4;
                    const int pos = pos16(ch & 15);
                    *(uint32_t*)(obH + ((size_t)y * WW + px) * NTOT + grp * 16 + pos) = pack_h2(v0, v1);
                    *(uint32_t*)(obH + ((size_t)y * WW + px + 8) * NTOT + grp * 16 + pos) = pack_h2(v2, v3);
                }
            }
        }
    }
}

// ================= conv1: 3->32 via packed f32x2 FMA, fp16 NHWC-permuted out =================
__global__ __launch_bounds__(256) void conv1_k(
    const float* __restrict__ x, const float* __restrict__ w,
    const float* __restrict__ bias, const float* __restrict__ pr,
    __half* __restrict__ out)
{
    __shared__ float s_in[3][10][34];
    __shared__ unsigned long long s_w2[27][16];   // (w[2j], w[2j+1]) per tap
    __shared__ float s_b[32];

    const int tid = threadIdx.x;
    const int tx = tid & 31, ty = tid >> 5;
    const int x0 = blockIdx.x * 32, y0 = blockIdx.y * 8;
    const int b = blockIdx.z;

    for (int i = tid; i < 432; i += 256) {
        const int t = i / 16, j = i % 16;
        const uint32_t lo = __float_as_uint(w[(2 * j) * 27 + t]);
        const uint32_t hi = __float_as_uint(w[(2 * j + 1) * 27 + t]);
        s_w2[t][j] = ((unsigned long long)hi << 32) | lo;
    }
    if (tid < 32) s_b[tid] = bias[tid];
    for (int i = tid; i < 1020; i += 256) {
        const int c = i / 340, r = i % 340;
        const int rr = r / 34, cc = r % 34;
        const int gy = y0 - 1 + rr, gx = x0 - 1 + cc;
        float v = 0.f;
        if ((unsigned)gy < HH && (unsigned)gx < WW)
            v = x[((size_t)(b * 3 + c)) * HW + (size_t)gy * WW + gx];
        s_in[c][rr][cc] = v;
    }
    __syncthreads();

    float vin[27];
    #pragma unroll
    for (int c = 0; c < 3; c++)
        #pragma unroll
        for (int dy = 0; dy < 3; dy++)
            #pragma unroll
            for (int dx = 0; dx < 3; dx++)
                vin[c * 9 + dy * 3 + dx] = s_in[c][ty + dy][tx + dx];

    unsigned long long acc2[16];
    #pragma unroll
    for (int j = 0; j < 16; j++) acc2[j] = 0ull;
    #pragma unroll
    for (int t = 0; t < 27; t++) {
        unsigned long long vv;
        asm("mov.b64 %0, {%1, %1};" : "=l"(vv) : "r"(__float_as_uint(vin[t])));
        #pragma unroll
        for (int j = 0; j < 16; j++) fma2(acc2[j], vv, s_w2[t][j]);
    }

    const float alpha = pr[0];
    uint32_t uu[16];
    #pragma unroll
    for (int j = 0; j < 16; j++) {
        uint32_t lo, hi;
        asm("mov.b64 {%0, %1}, %2;" : "=r"(lo), "=r"(hi) : "l"(acc2[j]));
        float v0 = __uint_as_float(lo) + s_b[2 * j];
        float v1 = __uint_as_float(hi) + s_b[2 * j + 1];
        if (v0 < 0.f) v0 *= alpha;
        if (v1 < 0.f) v1 *= alpha;
        const int jg = j & 7;
        const int slot = (j >> 3) * 8 + (jg & 3) * 2 + (jg >> 2);
        uu[slot] = pack_h2(v0, v1);
    }
    __half* dst = out + ((size_t)b * HW + (size_t)(y0 + ty) * WW + x0 + tx) * 32;
    #pragma unroll
    for (int q = 0; q < 4; q++)
        ((uint4*)dst)[q] = make_uint4(uu[4 * q], uu[4 * q + 1], uu[4 * q + 2], uu[4 * q + 3]);
}

// ================= GAP / SE =================
__global__ __launch_bounds__(256) void gapp_k(const float* __restrict__ hp, float* __restrict__ part)
{
    __shared__ float red[8][12];
    const int b = blockIdx.x, seg = blockIdx.y;
    const int tid = threadIdx.x;
    const float* base = hp + ((size_t)b * HW + (size_t)seg * (HW / 16)) * 16;
    float s[12];
    #pragma unroll
    for (int c = 0; c < 12; c++) s[c] = 0.f;
    for (int i = tid; i < HW / 16; i += 256) {
        const float4* q = (const float4*)(base + (size_t)i * 16);
        const float4 A = q[0], B4 = q[1], C = q[2];
        s[0] += A.x;  s[1] += A.y;  s[2] += A.z;  s[3] += A.w;
        s[4] += B4.x; s[5] += B4.y; s[6] += B4.z; s[7] += B4.w;
        s[8] += C.x;  s[9] += C.y;  s[10] += C.z; s[11] += C.w;
    }
    #pragma unroll
    for (int k = 16; k > 0; k >>= 1)
        #pragma unroll
        for (int c = 0; c < 12; c++) s[c] += __shfl_xor_sync(0xffffffffu, s[c], k);
    if ((tid & 31) == 0)
        #pragma unroll
        for (int c = 0; c < 12; c++) red[tid >> 5][c] = s[c];
    __syncthreads();
    if (tid < 12) {
        float t = 0.f;
        #pragma unroll
        for (int wdx = 0; wdx < 8; wdx++) t += red[wdx][tid];
        part[((size_t)b * 16 + seg) * 12 + tid] = t;
    }
}

__global__ void gapc_k(const float* __restrict__ part, float* __restrict__ g)
{
    const int t = threadIdx.x;
    if (t < 96) {
        const int b = t / 12, c = t % 12;
        float s = 0.f;
        #pragma unroll
        for (int k = 0; k < 16; k++) s += part[((size_t)b * 16 + k) * 12 + c];
        g[(c >> 2) * 32 + b * 4 + (c & 3)] = s * (1.0f / HW);
    }
}

__global__ void se_k(const float* __restrict__ g, const float* __restrict__ c1,
                     const float* __restrict__ c2, float* __restrict__ s)
{
    __shared__ float t[BB][4];
    int tid = threadIdx.x;
    if (tid < BB * 4) {
        int b = tid >> 2, c = tid & 3;
        float v = 0.f;
        #pragma unroll
        for (int k = 0; k < 4; k++) v += c1[c * 4 + k] * g[b * 4 + k];
        t[b][c] = fmaxf(v, 0.f);
    }
    __syncthreads();
    if (tid < BB * 4) {
        int b = tid >> 2, c = tid & 3;
        float v = 0.f;
        #pragma unroll
        for (int k = 0; k < 4; k++) v += c2[c * 4 + k] * t[b][k];
        s[b * 4 + c] = 1.f / (1.f + __expf(-v));
    }
}

// ================= fused blur + softmax + combine, 64x64 tiles =================
__global__ __launch_bounds__(256) void blurfuse_k(
    const float* __restrict__ src, const float* __restrict__ hp, int hoff,
    const float* __restrict__ sv, float* __restrict__ out)
{
    extern __shared__ float bsm[];
    float (*s_src)[89] = (float(*)[89])bsm;
    float (*s_h5)[84]  = (float(*)[84])(bsm + 88 * 89);
    float (*s_h15)[64] = (float(*)[64])(bsm + 88 * 89 + 88 * 84);
    float (*s_h25)[64] = (float(*)[64])(bsm + 88 * 89 + 88 * 84 + 88 * 64);

    const int tx = threadIdx.x, ty = threadIdx.y;
    const int tid = ty * 64 + tx;
    const int x0 = blockIdx.x * 64, y0 = blockIdx.y * 64;
    const int z = blockIdx.z;
    const int c = z % 3, b = z / 3;
    const size_t cb = (size_t)(b * 3 + c) * HW;

    for (int i = tid; i < 88 * 88; i += 256) {
        const int r = i / 88, cc = i % 88;
        const int gy = y0 - 12 + r, gx = x0 - 12 + cc;
        float v = 0.f;
        if ((unsigned)gy < HH && (unsigned)gx < WW)
            v = src[cb + (size_t)gy * WW + gx];
        s_src[r][cc] = v;
    }
    __syncthreads();

    for (int i = tid; i < 88 * 84; i += 256) {
        const int r = i / 84, j = i % 84;
        s_h5[r][j] = s_src[r][j] + s_src[r][j + 1] + s_src[r][j + 2]
                   + s_src[r][j + 3] + s_src[r][j + 4];
    }
    __syncthreads();

    for (int i = tid; i < 88 * 64; i += 256) {
        const int r = i / 64, t = i % 64;
        const float h15 = s_h5[r][t + 5] + s_h5[r][t + 10] + s_h5[r][t + 15];
        s_h15[r][t] = h15;
        s_h25[r][t] = h15 + s_h5[r][t] + s_h5[r][t + 20];
    }
    __syncthreads();

    const int r0 = ty * 16 + 12;
    float v5 = 0.f, v15 = 0.f, v25 = 0.f;
    #pragma unroll
    for (int d = -2; d <= 2; d++) v5 += s_h5[r0 + d][tx + 10];
    #pragma unroll
    for (int d = -7; d <= 7; d++) v15 += s_h15[r0 + d][tx];
    #pragma unroll
    for (int d = -12; d <= 12; d++) v25 += s_h25[r0 + d][tx];

    const float s0 = sv[b * 4 + 0], s1 = sv[b * 4 + 1], s2 = sv[b * 4 + 2], s3 = sv[b * 4 + 3];
    const int x = x0 + tx;

    #pragma unroll 1
    for (int j = 0; j < 16; j++) {
        const int y = y0 + ty * 16 + j;
        const int r = r0 + j;
        const float4 hv = *(const float4*)(hp + ((size_t)b * HW + (size_t)y * WW + x) * 16 + hoff);
        float e0 = hv.x * s0, e1 = hv.y * s1, e2 = hv.z * s2, e3 = hv.w * s3;
        float m = fmaxf(fmaxf(e0, e1), fmaxf(e2, e3));
        float w0 = __expf(e0 - m), w1 = __expf(e1 - m), w2 = __expf(e2 - m), w3 = __expf(e3 - m);
        float inv = 1.f / (w0 + w1 + w2 + w3);
        float o = (w0 * inv) * s_src[r][tx + 12]
                + (w1 * inv) * (v5 * (1.f / 25.f))
                + (w2 * inv) * (v15 * (1.f / 225.f))
                + (w3 * inv) * (v25 * (1.f / 625.f));
        out[cb + (size_t)y * WW + x] = o;
        if (j < 15) {
            v5 += s_h5[r + 3][tx + 10] - s_h5[r - 2][tx + 10];
            v15 += s_h15[r + 8][tx] - s_h15[r - 7][tx];
            v25 += s_h25[r + 13][tx] - s_h25[r - 12][tx];
        }
    }
}

// ================= launch =================
extern "C" void kernel_launch(void* const* d_in, const int* in_sizes, int n_in,
                              void* d_out, int out_size)
{
    const float* x   = (const float*)d_in[0];
    const float* bw1 = (const float*)d_in[1];
    const float* bb1 = (const float*)d_in[2];
    const float* a1  = (const float*)d_in[3];
    const float* bw2 = (const float*)d_in[4];
    const float* bb2 = (const float*)d_in[5];
    const float* a2  = (const float*)d_in[6];
    const float* bw3 = (const float*)d_in[7];
    const float* bb3 = (const float*)d_in[8];
    const float* a3  = (const float*)d_in[9];
    const float* hw_[3]  = { (const float*)d_in[10], (const float*)d_in[14], (const float*)d_in[18] };
    const float* hb_[3]  = { (const float*)d_in[11], (const float*)d_in[15], (const float*)d_in[19] };
    const float* hc1_[3] = { (const float*)d_in[12], (const float*)d_in[16], (const float*)d_in[20] };
    const float* hc2_[3] = { (const float*)d_in[13], (const float*)d_in[17], (const float*)d_in[21] };

    float *B1, *B2, *G, *P, *S, *TX, *TX2;
    uint2 *W2p, *W3p, *WHp;
    cudaGetSymbolAddress((void**)&B1, g_B1);
    cudaGetSymbolAddress((void**)&B2, g_B2);
    cudaGetSymbolAddress((void**)&G, g_G);
    cudaGetSymbolAddress((void**)&P, g_P);
    cudaGetSymbolAddress((void**)&S, g_S);
    cudaGetSymbolAddress((void**)&TX, g_TX);
    cudaGetSymbolAddress((void**)&TX2, g_TX2);
    cudaGetSymbolAddress((void**)&W2p, g_W2);
    cudaGetSymbolAddress((void**)&W3p, g_W3);
    cudaGetSymbolAddress((void**)&WHp, g_WH);
    __half* B1h = (__half*)B1;
    __half* B2h = (__half*)B2;

    const int smem2 = 4 * 2 * 258 * 32 + 9 * 2 * 64 * 32;  // 102912
    const int smem3 = 4 * 4 * 130 * 32 + 9 * 4 * 32 * 32;  // 103424
    const int smemH = 4 * 2 * 258 * 32 + 9 * 2 * 16 * 32;  // 75264
    const int smemF = (88 * 89 + 88 * 84 + 2 * 88 * 64) * 4;  // 105952
    cudaFuncSetAttribute((const void*)mconv_k<32, 64, 4, 4, 4, false>,
                         cudaFuncAttributeMaxDynamicSharedMemorySize, smem2);
    cudaFuncSetAttribute((const void*)mconv_k<64, 32, 4, 2, 2, false>,
                         cudaFuncAttributeMaxDynamicSharedMemorySize, smem3);
    cudaFuncSetAttribute((const void*)mconv_k<32, 16, 8, 2, 2, true>,
                         cudaFuncAttributeMaxDynamicSharedMemorySize, smemH);
    cudaFuncSetAttribute((const void*)blurfuse_k,
                         cudaFuncAttributeMaxDynamicSharedMemorySize, smemF);

    // ---- weight pre-transform (tiny) ----
    wprep_k<<<18, 256>>>(bw2, nullptr, nullptr, 32, 64, 0, W2p, 9 * 2 * 64 * 4);
    wprep_k<<<18, 256>>>(bw3, nullptr, nullptr, 64, 32, 0, W3p, 9 * 4 * 32 * 4);
    wprep_k<<<5, 256>>>(hw_[0], hw_[1], hw_[2], 32, 16, 1, WHp, 9 * 2 * 16 * 4);

    // ---- body ----
    conv1_k<<<dim3(16, 64, BB), 256>>>(x, bw1, bb1, a1, B1h);
    mconv_k<32, 64, 4, 4, 4, false><<<dim3(2, 64, BB), 256, smem2>>>(
        B1h, W2p, bb2, nullptr, nullptr, a2, B2h);
    mconv_k<64, 32, 4, 2, 2, false><<<dim3(4, 64, BB), 256, smem3>>>(
        B2h, W3p, bb3, nullptr, nullptr, a3, B1h);

    // ---- heads fused -> fp32 NHWC16 HPA (reuse B2) ----
    float* HPA = B2;
    mconv_k<32, 16, 8, 2, 2, true><<<dim3(2, 64, BB), 256, smemH>>>(
        B1h, WHp, hb_[0], hb_[1], hb_[2], nullptr, HPA);
    gapp_k<<<dim3(BB, 16), 256>>>(HPA, P);
    gapc_k<<<1, 128>>>(P, G);
    for (int i = 0; i < 3; i++)
        se_k<<<1, 32>>>(G + i * 32, hc1_[i], hc2_[i], S + i * 32);

    // ---- fused blur+softmax+combine (64x64 tiles, ping-pong) ----
    const dim3 fgrid(8, 8, BB * 3);
    const dim3 fblk(64, 4);
    blurfuse_k<<<fgrid, fblk, smemF>>>(x,   HPA, 0, S + 0,  TX);
    blurfuse_k<<<fgrid, fblk, smemF>>>(TX,  HPA, 4, S + 32, TX2);
    blurfuse_k<<<fgrid, fblk, smemF>>>(TX2, HPA, 8, S + 64, (float*)d_out);
    (void)in_sizes; (void)n_in; (void)out_size;
}

// round 9
// speedup vs baseline: 7.3301x; 1.0496x over previous
#include <cuda_runtime.h>
#include <cuda_fp16.h>
#include <cstdint>
#include <cstddef>

#define HH 512
#define WW 512
#define BB 8
constexpr int HW = HH * WW;
constexpr size_t SST = (size_t)BB * HW * 4;   // floats per head-stage buffer

// ---------------- scratch ----------------
__device__ float g_B1[(size_t)BB * HW * 32 / 2];   // fp16 NHWC-permuted 32ch
__device__ float g_B2[(size_t)BB * HW * 64];       // fp16 64ch / 3x packed HP stage buffers
__device__ float g_P[BB * 16 * 12];
__device__ float g_S[3 * BB * 4];
__device__ float g_TX[(size_t)BB * 3 * HW];
__device__ float g_TX2[(size_t)BB * 3 * HW];
__device__ uint2 g_W2[9 * 2 * 64 * 4];
__device__ uint2 g_W3[9 * 4 * 32 * 4];
__device__ uint2 g_WH[9 * 2 * 16 * 4];

// ---------------- helpers ----------------
__device__ __forceinline__ uint32_t smem_u32(const void* p) {
    uint32_t r;
    asm("{ .reg .u64 t; cvta.to.shared.u64 t, %1; cvt.u32.u64 %0, t; }" : "=r"(r) : "l"(p));
    return r;
}
__device__ __forceinline__ uint32_t pack_h2(float a, float b) {
    __half2 h = __floats2half2_rn(a, b);
    return *(uint32_t*)&h;
}
__device__ __forceinline__ void mma16(float* d, uint32_t a0, uint32_t a1, uint32_t a2,
                                      uint32_t a3, uint32_t b0, uint32_t b1) {
    asm volatile(
        "mma.sync.aligned.m16n8k16.row.col.f32.f16.f16.f32 "
        "{%0,%1,%2,%3}, {%4,%5,%6,%7}, {%8,%9}, {%0,%1,%2,%3};"
        : "+f"(d[0]), "+f"(d[1]), "+f"(d[2]), "+f"(d[3])
        : "r"(a0), "r"(a1), "r"(a2), "r"(a3), "r"(b0), "r"(b1));
}
__device__ __forceinline__ void fma2(unsigned long long& d, unsigned long long a,
                                     unsigned long long b) {
    asm("fma.rn.f32x2 %0, %1, %2, %0;" : "+l"(d) : "l"(a), "l"(b));
}
#define CP_A16(dst, src) asm volatile("cp.async.ca.shared.global [%0], [%1], 16;" :: "r"(dst), "l"(src) : "memory")
#define CP_COMMIT()      asm volatile("cp.async.commit_group;" ::: "memory")
#define CP_WAIT0()       asm volatile("cp.async.wait_group 0;" ::: "memory")
#define STZ16(dst)       asm volatile("st.shared.v4.b32 [%0], {%1,%1,%1,%1};" :: "r"(dst), "r"(0u) : "memory")

__device__ __forceinline__ constexpr int pos16(int c15) {
    return (((c15 >> 1) & 3) << 2) + (((c15 >> 1) >> 2) << 1) + (c15 & 1);
}

// ================= fused weight pre-transform (all three conv weight sets) =================
__device__ void wprep_one(const float* wA, const float* wB2, const float* wC,
                          int CIN, int NTOT, int H3, uint2* out, int i)
{
    const int NKS = CIN / 16;
    const int tap = i / (NKS * NTOT * 4);
    int r = i % (NKS * NTOT * 4);
    const int ks = r / (NTOT * 4);
    r %= NTOT * 4;
    const int n = r >> 2, t4 = r & 3;
    float v0 = 0.f, v1 = 0.f, v2 = 0.f, v3 = 0.f;
    const int cb = ks * 16 + t4 * 2;
    if (H3) {
        if (n < 12) {
            const float* wp = (n < 4) ? wA : (n < 8 ? wB2 : wC);
            const size_t nb = (size_t)(n & 3) * CIN;
            v0 = wp[(nb + cb) * 9 + tap];
            v1 = wp[(nb + cb + 1) * 9 + tap];
            v2 = wp[(nb + cb + 8) * 9 + tap];
            v3 = wp[(nb + cb + 9) * 9 + tap];
        }
    } else {
        const size_t nb = (size_t)n * CIN;
        v0 = wA[(nb + cb) * 9 + tap];
        v1 = wA[(nb + cb + 1) * 9 + tap];
        v2 = wA[(nb + cb + 8) * 9 + tap];
        v3 = wA[(nb + cb + 9) * 9 + tap];
    }
    uint2 e;
    e.x = pack_h2(v0, v1);
    e.y = pack_h2(v2, v3);
    out[i] = e;
}

__global__ void wprep_k(const float* __restrict__ w2, const float* __restrict__ w3,
                        const float* __restrict__ hA, const float* __restrict__ hB,
                        const float* __restrict__ hC,
                        uint2* __restrict__ o2, uint2* __restrict__ o3, uint2* __restrict__ oH)
{
    constexpr int T2 = 9 * 2 * 64 * 4;   // 4608
    constexpr int T3 = 9 * 4 * 32 * 4;   // 4608
    constexpr int TH = 9 * 2 * 16 * 4;   // 1152
    int i = blockIdx.x * 256 + threadIdx.x;
    if (i < T2) { wprep_one(w2, nullptr, nullptr, 32, 64, 0, o2, i); return; }
    i -= T2;
    if (i < T3) { wprep_one(w3, nullptr, nullptr, 64, 32, 0, o3, i); return; }
    i -= T3;
    if (i < TH) { wprep_one(hA, hB, hC, 32, 16, 1, oH, i); }
}

// ================= fp16 m16n8k16 3x3 conv =================
template<int CIN, int NTOT, int MW, int MT, int NT, bool H3>
__global__ __launch_bounds__(256) void mconv_k(
    const __half* __restrict__ in, const uint2* __restrict__ wp,
    const float* __restrict__ bA, const float* __restrict__ bB2, const float* __restrict__ bC,
    const float* __restrict__ pr, void* __restrict__ outv)
{
    constexpr int P = MW * MT * 16;
    constexpr int PP = P + 2;
    constexpr int NKS = CIN / 16;
    constexpr int SEGS = 2 * NKS;
    constexpr int SLOTU2 = NKS * PP * 4;
    constexpr int WSEGS = 9 * NKS * NTOT * 2;

    extern __shared__ __align__(16) char smraw[];
    const uint2* a_u2 = (const uint2*)smraw;
    const uint2* w_u2 = (const uint2*)smraw + 4 * SLOTU2;
    const uint32_t a_u = smem_u32(smraw);
    const uint32_t w_addr = a_u + (uint32_t)(4 * SLOTU2 * 8);

    const int tid = threadIdx.x;
    const int lane = tid & 31;
    const int wid = tid >> 5;
    const int g = lane >> 2, tg = lane & 3;
    const int mbase = (wid % MW) * MT * 16;
    const int nbase = (wid / MW) * NT * 8;
    const int x0 = blockIdx.x * P;
    const int y0 = blockIdx.y * 8;
    const int b = blockIdx.z;

    const __half* inb = in + (size_t)b * HW * CIN;

    auto stage = [&](int yy) {
        const int slot = (yy + 4) & 3;
        const uint32_t sbase = a_u + (uint32_t)(slot * SLOTU2 * 8);
        const bool rok = ((unsigned)yy < HH);
        const __half* rowp = inb + (size_t)yy * WW * CIN;
        for (int i = tid; i < PP * SEGS; i += 256) {
            const int p = i / SEGS;
            const int s = i % SEGS;
            const int ks = s >> 1, h = s & 1;
            const int gx = x0 + p - 1;
            const uint32_t dst = sbase + (uint32_t)(((ks * PP + p) * 32) + h * 16);
            if (rok && (unsigned)gx < WW)
                CP_A16(dst, rowp + (size_t)gx * CIN + ks * 16 + h * 8);
            else
                STZ16(dst);
        }
    };

    for (int i = tid; i < WSEGS; i += 256)
        CP_A16(w_addr + (uint32_t)i * 16, (const char*)wp + (size_t)i * 16);
    stage(y0 - 1); stage(y0); stage(y0 + 1);
    CP_COMMIT();

    __half* obH = (__half*)outv + (size_t)b * HW * NTOT;
    const float alpha = pr ? pr[0] : 0.f;

    #pragma unroll 1
    for (int yi = 0; yi < 8; yi++) {
        const int y = y0 + yi;
        CP_WAIT0();
        __syncthreads();
        if (yi < 7) { stage(y + 2); CP_COMMIT(); }

        float acc[MT][NT][4];
        #pragma unroll
        for (int mt = 0; mt < MT; mt++)
            #pragma unroll
            for (int nt = 0; nt < NT; nt++)
                #pragma unroll
                for (int e = 0; e < 4; e++) acc[mt][nt][e] = 0.f;

        #pragma unroll 1
        for (int tap = 0; tap < 9; tap++) {
            const int dy = tap / 3, dx = tap - dy * 3;
            const int slot = (y + dy + 3) & 3;
            #pragma unroll
            for (int ks = 0; ks < NKS; ks++) {
                const int base = (slot * NKS + ks) * PP * 4;
                uint2 q0[MT], q1[MT];
                #pragma unroll
                for (int mt = 0; mt < MT; mt++) {
                    const int pix = mbase + mt * 16 + g + dx;
                    q0[mt] = a_u2[base + pix * 4 + tg];
                    q1[mt] = a_u2[base + (pix + 8) * 4 + tg];
                }
                #pragma unroll
                for (int nt = 0; nt < NT; nt++) {
                    const uint2 qw = w_u2[((tap * NKS + ks) * NTOT + nbase + nt * 8 + g) * 4 + tg];
                    #pragma unroll
                    for (int mt = 0; mt < MT; mt++)
                        mma16(acc[mt][nt], q0[mt].x, q1[mt].x, q0[mt].y, q1[mt].y, qw.x, qw.y);
                }
            }
        }

        // ---- epilogue ----
        #pragma unroll
        for (int mt = 0; mt < MT; mt++) {
            const int px = x0 + mbase + mt * 16 + g;
            #pragma unroll
            for (int nt = 0; nt < NT; nt++) {
                const int ch = nbase + nt * 8 + tg * 2;   // even
                if (H3) {
                    if (ch < 12) {
                        const int st = ch >> 2, c4 = ch & 3;   // c4 in {0,2}
                        const float* bp = (st == 0) ? bA : (st == 1 ? bB2 : bC);
                        const float bv0 = bp[c4], bv1 = bp[c4 + 1];
                        float* hb = (float*)outv + st * SST + (size_t)b * HW * 4;
                        float2 lo = make_float2(acc[mt][nt][0] + bv0, acc[mt][nt][1] + bv1);
                        float2 hi = make_float2(acc[mt][nt][2] + bv0, acc[mt][nt][3] + bv1);
                        *(float2*)(hb + ((size_t)y * WW + px) * 4 + c4) = lo;
                        *(float2*)(hb + ((size_t)y * WW + px + 8) * 4 + c4) = hi;
                    }
                } else {
                    const float bv0 = bA[ch], bv1 = bA[ch + 1];
                    float v0 = acc[mt][nt][0] + bv0;
                    float v1 = acc[mt][nt][1] + bv1;
                    float v2 = acc[mt][nt][2] + bv0;
                    float v3 = acc[mt][nt][3] + bv1;
                    if (v0 < 0.f) v0 *= alpha;
                    if (v1 < 0.f) v1 *= alpha;
                    if (v2 < 0.f) v2 *= alpha;
                    if (v3 < 0.f) v3 *= alpha;
                    const int grp = ch >> 4;
                    const int pos = pos16(ch & 15);
                    *(uint32_t*)(obH + ((size_t)y * WW + px) * NTOT + grp * 16 + pos) = pack_h2(v0, v1);
                    *(uint32_t*)(obH + ((size_t)y * WW + px + 8) * NTOT + grp * 16 + pos) = pack_h2(v2, v3);
                }
            }
        }
    }
}

// ================= conv1: 3->32, f32x2 FMA + LDS.128 weights =================
__global__ __launch_bounds__(256) void conv1_k(
    const float* __restrict__ x, const float* __restrict__ w,
    const float* __restrict__ bias, const float* __restrict__ pr,
    __half* __restrict__ out)
{
    __shared__ float s_in[3][10][34];
    __shared__ ulonglong2 s_w4[27][8];   // [tap][j]: pairs (4j,4j+1) and (4j+2,4j+3)
    __shared__ float s_b[32];

    const int tid = threadIdx.x;
    const int tx = tid & 31, ty = tid >> 5;
    const int x0 = blockIdx.x * 32, y0 = blockIdx.y * 8;
    const int b = blockIdx.z;

    for (int i = tid; i < 216; i += 256) {
        const int t = i / 8, j = i % 8;
        const uint32_t a0 = __float_as_uint(w[(4 * j) * 27 + t]);
        const uint32_t a1 = __float_as_uint(w[(4 * j + 1) * 27 + t]);
        const uint32_t a2 = __float_as_uint(w[(4 * j + 2) * 27 + t]);
        const uint32_t a3 = __float_as_uint(w[(4 * j + 3) * 27 + t]);
        ulonglong2 e;
        e.x = ((unsigned long long)a1 << 32) | a0;
        e.y = ((unsigned long long)a3 << 32) | a2;
        s_w4[t][j] = e;
    }
    if (tid < 32) s_b[tid] = bias[tid];
    for (int i = tid; i < 1020; i += 256) {
        const int c = i / 340, r = i % 340;
        const int rr = r / 34, cc = r % 34;
        const int gy = y0 - 1 + rr, gx = x0 - 1 + cc;
        float v = 0.f;
        if ((unsigned)gy < HH && (unsigned)gx < WW)
            v = x[((size_t)(b * 3 + c)) * HW + (size_t)gy * WW + gx];
        s_in[c][rr][cc] = v;
    }
    __syncthreads();

    float vin[27];
    #pragma unroll
    for (int c = 0; c < 3; c++)
        #pragma unroll
        for (int dy = 0; dy < 3; dy++)
            #pragma unroll
            for (int dx = 0; dx < 3; dx++)
                vin[c * 9 + dy * 3 + dx] = s_in[c][ty + dy][tx + dx];

    unsigned long long acc2[16];
    #pragma unroll
    for (int j = 0; j < 16; j++) acc2[j] = 0ull;
    #pragma unroll
    for (int t = 0; t < 27; t++) {
        unsigned long long vv;
        asm("mov.b64 %0, {%1, %1};" : "=l"(vv) : "r"(__float_as_uint(vin[t])));
        #pragma unroll
        for (int j = 0; j < 8; j++) {
            const ulonglong2 ww = s_w4[t][j];
            fma2(acc2[2 * j], vv, ww.x);
            fma2(acc2[2 * j + 1], vv, ww.y);
        }
    }

    const float alpha = pr[0];
    uint32_t uu[16];
    #pragma unroll
    for (int j = 0; j < 16; j++) {
        uint32_t lo, hi;
        asm("mov.b64 {%0, %1}, %2;" : "=r"(lo), "=r"(hi) : "l"(acc2[j]));
        float v0 = __uint_as_float(lo) + s_b[2 * j];
        float v1 = __uint_as_float(hi) + s_b[2 * j + 1];
        if (v0 < 0.f) v0 *= alpha;
        if (v1 < 0.f) v1 *= alpha;
        const int jg = j & 7;
        const int slot = (j >> 3) * 8 + (jg & 3) * 2 + (jg >> 2);
        uu[slot] = pack_h2(v0, v1);
    }
    __half* dst = out + ((size_t)b * HW + (size_t)(y0 + ty) * WW + x0 + tx) * 32;
    #pragma unroll
    for (int q = 0; q < 4; q++)
        ((uint4*)dst)[q] = make_uint4(uu[4 * q], uu[4 * q + 1], uu[4 * q + 2], uu[4 * q + 3]);
}

// ================= GAP partials over 3 packed stage buffers =================
__global__ __launch_bounds__(256) void gapp_k(const float* __restrict__ hp, float* __restrict__ part)
{
    __shared__ float red[8][12];
    const int b = blockIdx.x, seg = blockIdx.y;
    const int tid = threadIdx.x;
    float s[12];
    #pragma unroll
    for (int c = 0; c < 12; c++) s[c] = 0.f;
    #pragma unroll
    for (int st = 0; st < 3; st++) {
        const float4* base = (const float4*)(hp + st * SST + ((size_t)b * HW + (size_t)seg * (HW / 16)) * 4);
        for (int i = tid; i < HW / 16; i += 256) {
            const float4 q = base[i];
            s[st * 4 + 0] += q.x; s[st * 4 + 1] += q.y;
            s[st * 4 + 2] += q.z; s[st * 4 + 3] += q.w;
        }
    }
    #pragma unroll
    for (int k = 16; k > 0; k >>= 1)
        #pragma unroll
        for (int c = 0; c < 12; c++) s[c] += __shfl_xor_sync(0xffffffffu, s[c], k);
    if ((tid & 31) == 0)
        #pragma unroll
        for (int c = 0; c < 12; c++) red[tid >> 5][c] = s[c];
    __syncthreads();
    if (tid < 12) {
        float t = 0.f;
        #pragma unroll
        for (int wdx = 0; wdx < 8; wdx++) t += red[wdx][tid];
        part[((size_t)b * 16 + seg) * 12 + tid] = t;
    }
}

// ================= fused GAP-combine + SE (all 3 stages) =================
__global__ void gapse_k(const float* __restrict__ part,
                        const float* __restrict__ c1a, const float* __restrict__ c2a,
                        const float* __restrict__ c1b, const float* __restrict__ c2b,
                        const float* __restrict__ c1c, const float* __restrict__ c2c,
                        float* __restrict__ sout)
{
    __shared__ float gg[8][12];
    __shared__ float tt[8][12];
    const int t = threadIdx.x;
    const int b = t / 12, c = t % 12;
    const int st = c >> 2, c4 = c & 3;
    const float* c1 = (st == 0) ? c1a : (st == 1 ? c1b : c1c);
    const float* c2 = (st == 0) ? c2a : (st == 1 ? c2b : c2c);
    if (t < 96) {
        float s = 0.f;
        #pragma unroll
        for (int k = 0; k < 16; k++) s += part[((size_t)b * 16 + k) * 12 + c];
        gg[b][c] = s * (1.0f / HW);
    }
    __syncthreads();
    if (t < 96) {
        float v = 0.f;
        #pragma unroll
        for (int k = 0; k < 4; k++) v += c1[c4 * 4 + k] * gg[b][st * 4 + k];
        tt[b][c] = fmaxf(v, 0.f);
    }
    __syncthreads();
    if (t < 96) {
        float v = 0.f;
        #pragma unroll
        for (int k = 0; k < 4; k++) v += c2[c4 * 4 + k] * tt[b][st * 4 + k];
        sout[st * 32 + b * 4 + c4] = 1.f / (1.f + __expf(-v));
    }
}

// ================= fused blur + softmax + combine, 64x64 tiles, packed hp =================
__global__ __launch_bounds__(256) void blurfuse_k(
    const float* __restrict__ src, const float* __restrict__ hp,
    const float* __restrict__ sv, float* __restrict__ out)
{
    extern __shared__ float bsm[];
    float (*s_src)[89] = (float(*)[89])bsm;
    float (*s_h5)[84]  = (float(*)[84])(bsm + 88 * 89);
    float (*s_h15)[64] = (float(*)[64])(bsm + 88 * 89 + 88 * 84);
    float (*s_h25)[64] = (float(*)[64])(bsm + 88 * 89 + 88 * 84 + 88 * 64);

    const int tx = threadIdx.x, ty = threadIdx.y;
    const int tid = ty * 64 + tx;
    const int x0 = blockIdx.x * 64, y0 = blockIdx.y * 64;
    const int z = blockIdx.z;
    const int c = z % 3, b = z / 3;
    const size_t cb = (size_t)(b * 3 + c) * HW;

    for (int i = tid; i < 88 * 88; i += 256) {
        const int r = i / 88, cc = i % 88;
        const int gy = y0 - 12 + r, gx = x0 - 12 + cc;
        float v = 0.f;
        if ((unsigned)gy < HH && (unsigned)gx < WW)
            v = src[cb + (size_t)gy * WW + gx];
        s_src[r][cc] = v;
    }
    __syncthreads();

    for (int i = tid; i < 88 * 84; i += 256) {
        const int r = i / 84, j = i % 84;
        s_h5[r][j] = s_src[r][j] + s_src[r][j + 1] + s_src[r][j + 2]
                   + s_src[r][j + 3] + s_src[r][j + 4];
    }
    __syncthreads();

    for (int i = tid; i < 88 * 64; i += 256) {
        const int r = i / 64, t = i % 64;
        const float h15 = s_h5[r][t + 5] + s_h5[r][t + 10] + s_h5[r][t + 15];
        s_h15[r][t] = h15;
        s_h25[r][t] = h15 + s_h5[r][t] + s_h5[r][t + 20];
    }
    __syncthreads();

    const int r0 = ty * 16 + 12;
    float v5 = 0.f, v15 = 0.f, v25 = 0.f;
    #pragma unroll
    for (int d = -2; d <= 2; d++) v5 += s_h5[r0 + d][tx + 10];
    #pragma unroll
    for (int d = -7; d <= 7; d++) v15 += s_h15[r0 + d][tx];
    #pragma unroll
    for (int d = -12; d <= 12; d++) v25 += s_h25[r0 + d][tx];

    const float s0 = sv[b * 4 + 0], s1 = sv[b * 4 + 1], s2 = sv[b * 4 + 2], s3 = sv[b * 4 + 3];
    const int x = x0 + tx;
    const float4* hppix = (const float4*)(hp + (size_t)b * HW * 4);

    #pragma unroll 1
    for (int j = 0; j < 16; j++) {
        const int y = y0 + ty * 16 + j;
        const int r = r0 + j;
        const float4 hv = hppix[(size_t)y * WW + x];
        float e0 = hv.x * s0, e1 = hv.y * s1, e2 = hv.z * s2, e3 = hv.w * s3;
        float m = fmaxf(fmaxf(e0, e1), fmaxf(e2, e3));
        float w0 = __expf(e0 - m), w1 = __expf(e1 - m), w2 = __expf(e2 - m), w3 = __expf(e3 - m);
        float inv = 1.f / (w0 + w1 + w2 + w3);
        float o = (w0 * inv) * s_src[r][tx + 12]
                + (w1 * inv) * (v5 * (1.f / 25.f))
                + (w2 * inv) * (v15 * (1.f / 225.f))
                + (w3 * inv) * (v25 * (1.f / 625.f));
        out[cb + (size_t)y * WW + x] = o;
        if (j < 15) {
            v5 += s_h5[r + 3][tx + 10] - s_h5[r - 2][tx + 10];
            v15 += s_h15[r + 8][tx] - s_h15[r - 7][tx];
            v25 += s_h25[r + 13][tx] - s_h25[r - 12][tx];
        }
    }
}

// ================= launch =================
extern "C" void kernel_launch(void* const* d_in, const int* in_sizes, int n_in,
                              void* d_out, int out_size)
{
    const float* x   = (const float*)d_in[0];
    const float* bw1 = (const float*)d_in[1];
    const float* bb1 = (const float*)d_in[2];
    const float* a1  = (const float*)d_in[3];
    const float* bw2 = (const float*)d_in[4];
    const float* bb2 = (const float*)d_in[5];
    const float* a2  = (const float*)d_in[6];
    const float* bw3 = (const float*)d_in[7];
    const float* bb3 = (const float*)d_in[8];
    const float* a3  = (const float*)d_in[9];
    const float* hw_[3]  = { (const float*)d_in[10], (const float*)d_in[14], (const float*)d_in[18] };
    const float* hb_[3]  = { (const float*)d_in[11], (const float*)d_in[15], (const float*)d_in[19] };
    const float* hc1_[3] = { (const float*)d_in[12], (const float*)d_in[16], (const float*)d_in[20] };
    const float* hc2_[3] = { (const float*)d_in[13], (const float*)d_in[17], (const float*)d_in[21] };

    float *B1, *B2, *P, *S, *TX, *TX2;
    uint2 *W2p, *W3p, *WHp;
    cudaGetSymbolAddress((void**)&B1, g_B1);
    cudaGetSymbolAddress((void**)&B2, g_B2);
    cudaGetSymbolAddress((void**)&P, g_P);
    cudaGetSymbolAddress((void**)&S, g_S);
    cudaGetSymbolAddress((void**)&TX, g_TX);
    cudaGetSymbolAddress((void**)&TX2, g_TX2);
    cudaGetSymbolAddress((void**)&W2p, g_W2);
    cudaGetSymbolAddress((void**)&W3p, g_W3);
    cudaGetSymbolAddress((void**)&WHp, g_WH);
    __half* B1h = (__half*)B1;
    __half* B2h = (__half*)B2;

    const int smem2 = 4 * 2 * 258 * 32 + 9 * 2 * 64 * 32;  // 102912
    const int smem3 = 4 * 4 * 130 * 32 + 9 * 4 * 32 * 32;  // 103424
    const int smemH = 4 * 2 * 258 * 32 + 9 * 2 * 16 * 32;  // 75264
    const int smemF = (88 * 89 + 88 * 84 + 2 * 88 * 64) * 4;  // 105952
    cudaFuncSetAttribute((const void*)mconv_k<32, 64, 4, 4, 4, false>,
                         cudaFuncAttributeMaxDynamicSharedMemorySize, smem2);
    cudaFuncSetAttribute((const void*)mconv_k<64, 32, 4, 2, 2, false>,
                         cudaFuncAttributeMaxDynamicSharedMemorySize, smem3);
    cudaFuncSetAttribute((const void*)mconv_k<32, 16, 8, 2, 2, true>,
                         cudaFuncAttributeMaxDynamicSharedMemorySize, smemH);
    cudaFuncSetAttribute((const void*)blurfuse_k,
                         cudaFuncAttributeMaxDynamicSharedMemorySize, smemF);

    // ---- weight pre-transform (one kernel) ----
    wprep_k<<<(4608 + 4608 + 1152 + 255) / 256, 256>>>(bw2, bw3, hw_[0], hw_[1], hw_[2],
                                                       W2p, W3p, WHp);

    // ---- body ----
    conv1_k<<<dim3(16, 64, BB), 256>>>(x, bw1, bb1, a1, B1h);
    mconv_k<32, 64, 4, 4, 4, false><<<dim3(2, 64, BB), 256, smem2>>>(
        B1h, W2p, bb2, nullptr, nullptr, a2, B2h);
    mconv_k<64, 32, 4, 2, 2, false><<<dim3(4, 64, BB), 256, smem3>>>(
        B2h, W3p, bb3, nullptr, nullptr, a3, B1h);

    // ---- heads -> 3 packed stage buffers in B2 ----
    float* HP = B2;
    mconv_k<32, 16, 8, 2, 2, true><<<dim3(2, 64, BB), 256, smemH>>>(
        B1h, WHp, hb_[0], hb_[1], hb_[2], nullptr, HP);
    gapp_k<<<dim3(BB, 16), 256>>>(HP, P);
    gapse_k<<<1, 96>>>(P, hc1_[0], hc2_[0], hc1_[1], hc2_[1], hc1_[2], hc2_[2], S);

    // ---- fused blur+softmax+combine (ping-pong) ----
    const dim3 fgrid(8, 8, BB * 3);
    const dim3 fblk(64, 4);
    blurfuse_k<<<fgrid, fblk, smemF>>>(x,   HP + 0 * SST, S + 0,  TX);
    blurfuse_k<<<fgrid, fblk, smemF>>>(TX,  HP + 1 * SST, S + 32, TX2);
    blurfuse_k<<<fgrid, fblk, smemF>>>(TX2, HP + 2 * SST, S + 64, (float*)d_out);
    (void)in_sizes; (void)n_in; (void)out_size;
}